// round 1
// baseline (speedup 1.0000x reference)
#include <cuda_runtime.h>
#include <math.h>
#include <math_constants.h>

// ---------------- problem constants ----------------
#define DIMV   2048
#define SEQ    2048
#define BATCH  4
#define NHEAD  16
#define NKV    4
#define HD     128
#define HALF   64
#define QKVW   (DIMV + 2 * NKV * HD)   // 3072
#define NTOK   (BATCH * SEQ)           // 8192
#define RMS_EPS 1.1920929e-07f
#define ATT_SCALE 0.08838834764831845f // 1/sqrt(128)

// ---------------- scratch (static device globals; no allocation) ----------------
__device__ float g_qkv[(size_t)NTOK * QKVW];   // 96 MB
__device__ float g_y[(size_t)NTOK * DIMV];     // 64 MB
__device__ float g_cos[SEQ * HALF];
__device__ float g_sin[SEQ * HALF];

// ================= RoPE table (double-precision angles) =================
__global__ void rope_table_kernel(float* __restrict__ ct, float* __restrict__ st) {
    int idx = blockIdx.x * blockDim.x + threadIdx.x;
    if (idx >= SEQ * HALF) return;
    int s = idx >> 6;
    int f = idx & 63;
    double inv = pow(10000.0, -((double)(2 * f)) / 128.0);
    double th = (double)s * inv;
    ct[idx] = (float)cos(th);
    st[idx] = (float)sin(th);
}

// ================= SGEMM: C[M,N] = A[M,K] @ B[K,N], row-major =================
// 128x128 tile, BK=8, 256 threads, 8x8 per thread (2x2 quadrants of 4x4)
__global__ __launch_bounds__(256) void sgemm_kernel(
    const float* __restrict__ A, const float* __restrict__ B, float* __restrict__ C,
    int M, int N, int K)
{
    __shared__ float As[8][132];   // As[kk][m]  (transposed A tile)
    __shared__ float Bs[8][132];   // Bs[kk][n]

    const int tid = threadIdx.x;
    const int tx = tid & 15;       // 16 col groups
    const int ty = tid >> 4;       // 16 row groups
    const int row0 = blockIdx.y * 128;
    const int col0 = blockIdx.x * 128;

    const int aRow = tid >> 1;         // 0..127
    const int aCol = (tid & 1) * 4;    // 0 or 4
    const int bRow = tid >> 5;         // 0..7
    const int bCol = (tid & 31) * 4;   // 0..124

    const float* Aptr = A + (size_t)(row0 + aRow) * K + aCol;
    const float* Bptr = B + (size_t)bRow * N + col0 + bCol;

    float acc[8][8];
#pragma unroll
    for (int i = 0; i < 8; i++)
#pragma unroll
        for (int j = 0; j < 8; j++) acc[i][j] = 0.f;

    for (int k0 = 0; k0 < K; k0 += 8) {
        float4 a = *(const float4*)(Aptr + k0);
        As[aCol + 0][aRow] = a.x;
        As[aCol + 1][aRow] = a.y;
        As[aCol + 2][aRow] = a.z;
        As[aCol + 3][aRow] = a.w;
        float4 b = *(const float4*)(Bptr + (size_t)k0 * N);
        *(float4*)&Bs[bRow][bCol] = b;
        __syncthreads();

#pragma unroll
        for (int kk = 0; kk < 8; kk++) {
            float a0[4], a1[4], b0[4], b1[4];
            *(float4*)a0 = *(const float4*)&As[kk][ty * 4];
            *(float4*)a1 = *(const float4*)&As[kk][64 + ty * 4];
            *(float4*)b0 = *(const float4*)&Bs[kk][tx * 4];
            *(float4*)b1 = *(const float4*)&Bs[kk][64 + tx * 4];
#pragma unroll
            for (int i = 0; i < 4; i++) {
#pragma unroll
                for (int j = 0; j < 4; j++) {
                    acc[i][j]         += a0[i] * b0[j];
                    acc[i][4 + j]     += a0[i] * b1[j];
                    acc[4 + i][j]     += a1[i] * b0[j];
                    acc[4 + i][4 + j] += a1[i] * b1[j];
                }
            }
        }
        __syncthreads();
    }

#pragma unroll
    for (int rm = 0; rm < 2; rm++) {
#pragma unroll
        for (int i = 0; i < 4; i++) {
            float* c = C + (size_t)(row0 + rm * 64 + ty * 4 + i) * N + col0;
            int r = rm * 4 + i;
            *(float4*)(c + tx * 4)      = make_float4(acc[r][0], acc[r][1], acc[r][2], acc[r][3]);
            *(float4*)(c + 64 + tx * 4) = make_float4(acc[r][4], acc[r][5], acc[r][6], acc[r][7]);
        }
    }
}

// ================= RMS-norm + RoPE, in place over g_qkv =================
// grid (NTOK, 20): hh 0..15 -> q heads, 16..19 -> k heads. 128 threads/block.
__global__ __launch_bounds__(128) void rmsrope_kernel(
    float* __restrict__ qkv, const float* __restrict__ ct, const float* __restrict__ st)
{
    const int row = blockIdx.x;          // token index (b*SEQ + s)
    const int hh = blockIdx.y;
    const int s = row & (SEQ - 1);
    const int col = (hh < NHEAD) ? hh * HD : DIMV + (hh - NHEAD) * HD;
    float* p = qkv + (size_t)row * QKVW + col;
    const int t = threadIdx.x;

    float v = p[t];
    float sq = v * v;
#pragma unroll
    for (int off = 16; off; off >>= 1) sq += __shfl_xor_sync(0xffffffffu, sq, off);

    __shared__ float red[4];
    __shared__ float xs[128];
    if ((t & 31) == 0) red[t >> 5] = sq;
    __syncthreads();
    float total = red[0] + red[1] + red[2] + red[3];
    float sc = rsqrtf(total * (1.0f / 128.0f) + RMS_EPS);
    float xn = v * sc;
    xs[t] = xn;
    __syncthreads();

    float out;
    if (t < HALF) {
        float c = ct[s * HALF + t], sn = st[s * HALF + t];
        out = xn * c + xs[t + HALF] * sn;          // x1*cos + x2*sin
    } else {
        int f = t - HALF;
        float c = ct[s * HALF + f], sn = st[s * HALF + f];
        out = xn * c - xs[f] * sn;                 // x2*cos - x1*sin
    }
    p[t] = out;
}

// ================= Flash attention fp32 (BM=BN=64, D=128, GQA causal) =================
// grid (SEQ/64, BATCH*NHEAD), 256 threads. Dynamic smem.
// smem layout (floats): Qt[128][65] | Kt[128][65] | Vs[64][132] | Pt[64][68]
#define ATT_SMEM_FLOATS (128 * 65 * 2 + 64 * 132 + 64 * 68)
#define ATT_SMEM_BYTES  (ATT_SMEM_FLOATS * 4)

__global__ __launch_bounds__(256) void attn_kernel(
    const float* __restrict__ qkv, float* __restrict__ y)
{
    extern __shared__ float sm[];
    float* Qt = sm;                       // [128][65]  Qt[kk*65 + r]
    float* Kt = Qt + 128 * 65;            // [128][65]
    float* Vs = Kt + 128 * 65;            // [64][132]  Vs[j*132 + d]
    float* Pt = Vs + 64 * 132;            // [64][68]   Pt[j*68 + r]

    const int tid = threadIdx.x;
    const int tx = tid & 15;
    const int ty = tid >> 4;
    const int i0 = blockIdx.x * 64;
    const int bh = blockIdx.y;
    const int b = bh >> 4;
    const int h = bh & 15;
    const int kvh = h >> 2;

    const size_t rowbase = (size_t)b * SEQ * QKVW;
    const int kcol = DIMV + kvh * HD;
    const int vcol = DIMV + NKV * HD + kvh * HD;

    // load Q tile (scaled) transposed into Qt
    {
        int r0 = tid >> 5;
        int c4 = (tid & 31) * 4;
        for (int rr = r0; rr < 64; rr += 8) {
            const float* src = qkv + rowbase + (size_t)(i0 + rr) * QKVW + h * HD + c4;
            float4 v = *(const float4*)src;
            Qt[(c4 + 0) * 65 + rr] = v.x * ATT_SCALE;
            Qt[(c4 + 1) * 65 + rr] = v.y * ATT_SCALE;
            Qt[(c4 + 2) * 65 + rr] = v.z * ATT_SCALE;
            Qt[(c4 + 3) * 65 + rr] = v.w * ATT_SCALE;
        }
    }

    float m_i[4], l_i[4], o[4][2][4];
#pragma unroll
    for (int i = 0; i < 4; i++) {
        m_i[i] = -CUDART_INF_F;
        l_i[i] = 0.f;
#pragma unroll
        for (int q = 0; q < 2; q++)
#pragma unroll
            for (int u = 0; u < 4; u++) o[i][q][u] = 0.f;
    }

    for (int j0 = 0; j0 <= i0; j0 += 64) {
        __syncthreads();   // previous PV readers done (also publishes Q on 1st iter)
        // load K (transposed) and V tiles
        {
            int r0 = tid >> 5;
            int c4 = (tid & 31) * 4;
            for (int rr = r0; rr < 64; rr += 8) {
                const float* ks = qkv + rowbase + (size_t)(j0 + rr) * QKVW + kcol + c4;
                float4 kv4 = *(const float4*)ks;
                Kt[(c4 + 0) * 65 + rr] = kv4.x;
                Kt[(c4 + 1) * 65 + rr] = kv4.y;
                Kt[(c4 + 2) * 65 + rr] = kv4.z;
                Kt[(c4 + 3) * 65 + rr] = kv4.w;
                const float* vsrc = qkv + rowbase + (size_t)(j0 + rr) * QKVW + vcol + c4;
                *(float4*)&Vs[rr * 132 + c4] = *(const float4*)vsrc;
            }
        }
        __syncthreads();

        // ---- S = Q K^T (per-thread 4 rows x 4 cols) ----
        float scv[4][4];
#pragma unroll
        for (int i = 0; i < 4; i++)
#pragma unroll
            for (int u = 0; u < 4; u++) scv[i][u] = 0.f;

#pragma unroll 4
        for (int kk = 0; kk < 128; kk++) {
            const float* qrow = &Qt[kk * 65 + ty * 4];
            float qv[4] = {qrow[0], qrow[1], qrow[2], qrow[3]};
            const float* krow = &Kt[kk * 65];
            float kv[4] = {krow[tx * 2], krow[tx * 2 + 1], krow[32 + tx * 2], krow[33 + tx * 2]};
#pragma unroll
            for (int i = 0; i < 4; i++)
#pragma unroll
                for (int u = 0; u < 4; u++) scv[i][u] += qv[i] * kv[u];
        }

        // causal mask (diagonal tile only)
        if (j0 == i0) {
#pragma unroll
            for (int i = 0; i < 4; i++) {
                int rloc = ty * 4 + i;
#pragma unroll
                for (int u = 0; u < 4; u++) {
                    int cloc = ((u >> 1) << 5) + tx * 2 + (u & 1);
                    if (cloc > rloc) scv[i][u] = -CUDART_INF_F;
                }
            }
        }

        // ---- online softmax (rows owned by 16-lane groups sharing ty) ----
#pragma unroll
        for (int i = 0; i < 4; i++) {
            float mt = fmaxf(fmaxf(scv[i][0], scv[i][1]), fmaxf(scv[i][2], scv[i][3]));
#pragma unroll
            for (int off = 8; off >= 1; off >>= 1)
                mt = fmaxf(mt, __shfl_xor_sync(0xffffffffu, mt, off));
            float mnew = fmaxf(m_i[i], mt);
            float alpha = expf(m_i[i] - mnew);
            m_i[i] = mnew;
            float p[4], rs = 0.f;
#pragma unroll
            for (int u = 0; u < 4; u++) { p[u] = expf(scv[i][u] - mnew); rs += p[u]; }
#pragma unroll
            for (int off = 8; off >= 1; off >>= 1)
                rs += __shfl_xor_sync(0xffffffffu, rs, off);
            l_i[i] = l_i[i] * alpha + rs;
#pragma unroll
            for (int q = 0; q < 2; q++)
#pragma unroll
                for (int u = 0; u < 4; u++) o[i][q][u] *= alpha;
            // store probs transposed: Pt[col][row]
#pragma unroll
            for (int u = 0; u < 4; u++) {
                int cloc = ((u >> 1) << 5) + tx * 2 + (u & 1);
                Pt[cloc * 68 + ty * 4 + i] = p[u];
            }
        }
        __syncthreads();

        // ---- O += P V  (rows ty*4.., cols quadrant q*64 + tx*4..) ----
#pragma unroll 2
        for (int j = 0; j < 64; j++) {
            float4 pv = *(const float4*)&Pt[j * 68 + ty * 4];
            float4 v0 = *(const float4*)&Vs[j * 132 + tx * 4];
            float4 v1 = *(const float4*)&Vs[j * 132 + 64 + tx * 4];
            float pr[4] = {pv.x, pv.y, pv.z, pv.w};
            float va[2][4] = {{v0.x, v0.y, v0.z, v0.w}, {v1.x, v1.y, v1.z, v1.w}};
#pragma unroll
            for (int i = 0; i < 4; i++)
#pragma unroll
                for (int q = 0; q < 2; q++)
#pragma unroll
                    for (int u = 0; u < 4; u++) o[i][q][u] += pr[i] * va[q][u];
        }
    }

    // normalize and write y in (b, s, head, d) layout
#pragma unroll
    for (int i = 0; i < 4; i++) {
        float inv = 1.0f / l_i[i];
        int srow = i0 + ty * 4 + i;
        float* dst = y + (size_t)(b * SEQ + srow) * DIMV + h * HD;
#pragma unroll
        for (int q = 0; q < 2; q++) {
            float4 v = make_float4(o[i][q][0] * inv, o[i][q][1] * inv,
                                   o[i][q][2] * inv, o[i][q][3] * inv);
            *(float4*)(dst + q * 64 + tx * 4) = v;
        }
    }
}

// ================= launch =================
extern "C" void kernel_launch(void* const* d_in, const int* in_sizes, int n_in,
                              void* d_out, int out_size)
{
    const float* x    = (const float*)d_in[0];
    const float* Wqkv = (const float*)d_in[1];
    const float* Wout = (const float*)d_in[2];
    float* out = (float*)d_out;

    float *qkv, *y, *ct, *st;
    cudaGetSymbolAddress((void**)&qkv, g_qkv);
    cudaGetSymbolAddress((void**)&y,   g_y);
    cudaGetSymbolAddress((void**)&ct,  g_cos);
    cudaGetSymbolAddress((void**)&st,  g_sin);

    // 1. RoPE tables
    rope_table_kernel<<<(SEQ * HALF + 255) / 256, 256>>>(ct, st);

    // 2. QKV projection: [8192,2048] @ [2048,3072]
    sgemm_kernel<<<dim3(QKVW / 128, NTOK / 128), 256>>>(x, Wqkv, qkv, NTOK, QKVW, DIMV);

    // 3. RMS-norm + RoPE on q and k heads (in place)
    rmsrope_kernel<<<dim3(NTOK, NHEAD + NKV), 128>>>(qkv, ct, st);

    // 4. causal GQA flash attention
    cudaFuncSetAttribute(attn_kernel, cudaFuncAttributeMaxDynamicSharedMemorySize, ATT_SMEM_BYTES);
    attn_kernel<<<dim3(SEQ / 64, BATCH * NHEAD), 256, ATT_SMEM_BYTES>>>(qkv, y);

    // 5. output projection: [8192,2048] @ [2048,2048]
    sgemm_kernel<<<dim3(DIMV / 128, NTOK / 128), 256>>>(y, Wout, out, NTOK, DIMV, DIMV);
}

// round 2
// speedup vs baseline: 1.6515x; 1.6515x over previous
#include <cuda_runtime.h>
#include <math.h>
#include <math_constants.h>

// ---------------- problem constants ----------------
#define DIMV   2048
#define SEQ    2048
#define BATCH  4
#define NHEAD  16
#define NKV    4
#define HD     128
#define HALF   64
#define QKVW   (DIMV + 2 * NKV * HD)   // 3072
#define NTOK   (BATCH * SEQ)           // 8192
#define RMS_EPS 1.1920929e-07f
#define ATT_SCALE 0.08838834764831845f // 1/sqrt(128)

// ---------------- scratch (static device globals; no allocation) ----------------
__device__ float g_qkv[(size_t)NTOK * QKVW];   // 96 MB
__device__ float g_y[(size_t)NTOK * DIMV];     // 64 MB
__device__ float g_cos[SEQ * HALF];
__device__ float g_sin[SEQ * HALF];

// ================= RoPE table (double-precision angles) =================
__global__ void rope_table_kernel(float* __restrict__ ct, float* __restrict__ st) {
    int idx = blockIdx.x * blockDim.x + threadIdx.x;
    if (idx >= SEQ * HALF) return;
    int s = idx >> 6;
    int f = idx & 63;
    double inv = pow(10000.0, -((double)(2 * f)) / 128.0);
    double th = (double)s * inv;
    ct[idx] = (float)cos(th);
    st[idx] = (float)sin(th);
}

// ======================================================================
// TF32 tensor-core GEMM: C[M,N] = A[M,K] @ B[K,N], row-major, fp32 in/out
// CTA tile 128x256, BK=16, 4-stage cp.async pipeline, 8 warps (2x4),
// warp tile 64x64 via mma.sync.m16n8k8 tf32.
// ======================================================================
#define BM 128
#define BN 256
#define BK 16
#define STAGES 4
// smem strides chosen for conflict-free fragment loads:
// A stored row-major [m][k] stride 20; B row-major [k][n] stride 264.
#define A_STRIDE 20
#define B_STRIDE 264
#define A_FLOATS (BM * A_STRIDE)          // 2560
#define B_FLOATS (BK * B_STRIDE)          // 4224
#define STAGE_FLOATS (A_FLOATS + B_FLOATS) // 6784
#define GEMM_SMEM_BYTES (STAGES * STAGE_FLOATS * 4)  // 108544

__device__ __forceinline__ unsigned f2tf32(float f) {
    unsigned r;
    asm("cvt.rna.tf32.f32 %0, %1;" : "=r"(r) : "f"(f));
    return r;
}

__device__ __forceinline__ void cp_async16(void* dst_smem, const void* src_gmem) {
    unsigned d = (unsigned)__cvta_generic_to_shared(dst_smem);
    asm volatile("cp.async.cg.shared.global [%0], [%1], 16;\n" :: "r"(d), "l"(src_gmem));
}
#define CP_COMMIT asm volatile("cp.async.commit_group;\n" ::: "memory")
#define CP_WAIT2  asm volatile("cp.async.wait_group 2;\n" ::: "memory")

__device__ __forceinline__ void mma_tf32(float* c, const unsigned* a, const unsigned* b) {
    asm volatile(
        "mma.sync.aligned.m16n8k8.row.col.f32.tf32.tf32.f32 "
        "{%0,%1,%2,%3}, {%4,%5,%6,%7}, {%8,%9}, {%0,%1,%2,%3};\n"
        : "+f"(c[0]), "+f"(c[1]), "+f"(c[2]), "+f"(c[3])
        : "r"(a[0]), "r"(a[1]), "r"(a[2]), "r"(a[3]), "r"(b[0]), "r"(b[1]));
}

__global__ __launch_bounds__(256, 1) void gemm_tf32_kernel(
    const float* __restrict__ A, const float* __restrict__ B, float* __restrict__ C,
    int M, int N, int K)
{
    extern __shared__ float sm[];
    const int tid = threadIdx.x;
    const int warp = tid >> 5;
    const int lane = tid & 31;
    const int grp = lane >> 2;      // 0..7
    const int tig = lane & 3;       // 0..3
    const int wm = warp >> 2;       // 0..1  (64-row band)
    const int wn = warp & 3;        // 0..3  (64-col band)
    const int row0 = blockIdx.y * BM;
    const int col0 = blockIdx.x * BN;

    const int NIT = K / BK;

    // ---- async load of one stage ----
    auto issue_load = [&](int buf, int k0) {
        float* sA = sm + buf * STAGE_FLOATS;
        float* sB = sA + A_FLOATS;
#pragma unroll
        for (int rep = 0; rep < 2; rep++) {
            int idx = tid + rep * 256;            // 0..511
            int m = idx >> 2, kq = (idx & 3) * 4;
            cp_async16(sA + m * A_STRIDE + kq,
                       A + (size_t)(row0 + m) * K + k0 + kq);
        }
#pragma unroll
        for (int rep = 0; rep < 4; rep++) {
            int idx = tid + rep * 256;            // 0..1023
            int k = idx >> 6, nq = (idx & 63) * 4;
            cp_async16(sB + k * B_STRIDE + nq,
                       B + (size_t)(k0 + k) * N + col0 + nq);
        }
    };

    float acc[4][8][4];
#pragma unroll
    for (int mt = 0; mt < 4; mt++)
#pragma unroll
        for (int nt = 0; nt < 8; nt++)
#pragma unroll
            for (int r = 0; r < 4; r++) acc[mt][nt][r] = 0.f;

    // prologue: 3 stages in flight
#pragma unroll
    for (int s = 0; s < STAGES - 1; s++) {
        issue_load(s, s * BK);
        CP_COMMIT;
    }

    for (int it = 0; it < NIT; it++) {
        CP_WAIT2;
        __syncthreads();

        if (it + STAGES - 1 < NIT)
            issue_load((it + STAGES - 1) & (STAGES - 1), (it + STAGES - 1) * BK);
        CP_COMMIT;

        const float* sA = sm + (it & (STAGES - 1)) * STAGE_FLOATS;
        const float* sB = sA + A_FLOATS;

#pragma unroll
        for (int ks = 0; ks < 2; ks++) {
            unsigned af[4][4], bf[8][2];
            const int kk = ks * 8 + tig;
#pragma unroll
            for (int mt = 0; mt < 4; mt++) {
                const float* ap = sA + (wm * 64 + mt * 16 + grp) * A_STRIDE + kk;
                af[mt][0] = f2tf32(ap[0]);
                af[mt][1] = f2tf32(ap[8 * A_STRIDE]);
                af[mt][2] = f2tf32(ap[4]);
                af[mt][3] = f2tf32(ap[8 * A_STRIDE + 4]);
            }
#pragma unroll
            for (int nt = 0; nt < 8; nt++) {
                const float* bp = sB + kk * B_STRIDE + wn * 64 + nt * 8 + grp;
                bf[nt][0] = f2tf32(bp[0]);
                bf[nt][1] = f2tf32(bp[4 * B_STRIDE]);
            }
#pragma unroll
            for (int mt = 0; mt < 4; mt++)
#pragma unroll
                for (int nt = 0; nt < 8; nt++)
                    mma_tf32(acc[mt][nt], af[mt], bf[nt]);
        }
        __syncthreads();
    }

    // ---- epilogue: c frag rows = grp(+8), cols = tig*2(+1) ----
#pragma unroll
    for (int mt = 0; mt < 4; mt++) {
        int row = row0 + wm * 64 + mt * 16 + grp;
#pragma unroll
        for (int nt = 0; nt < 8; nt++) {
            int col = col0 + wn * 64 + nt * 8 + tig * 2;
            float* c0 = C + (size_t)row * N + col;
            float* c1 = C + (size_t)(row + 8) * N + col;
            *(float2*)c0 = make_float2(acc[mt][nt][0], acc[mt][nt][1]);
            *(float2*)c1 = make_float2(acc[mt][nt][2], acc[mt][nt][3]);
        }
    }
}

// ================= RMS-norm + RoPE, in place over g_qkv =================
__global__ __launch_bounds__(128) void rmsrope_kernel(
    float* __restrict__ qkv, const float* __restrict__ ct, const float* __restrict__ st)
{
    const int row = blockIdx.x;          // token index (b*SEQ + s)
    const int hh = blockIdx.y;
    const int s = row & (SEQ - 1);
    const int col = (hh < NHEAD) ? hh * HD : DIMV + (hh - NHEAD) * HD;
    float* p = qkv + (size_t)row * QKVW + col;
    const int t = threadIdx.x;

    float v = p[t];
    float sq = v * v;
#pragma unroll
    for (int off = 16; off; off >>= 1) sq += __shfl_xor_sync(0xffffffffu, sq, off);

    __shared__ float red[4];
    __shared__ float xs[128];
    if ((t & 31) == 0) red[t >> 5] = sq;
    __syncthreads();
    float total = red[0] + red[1] + red[2] + red[3];
    float sc = rsqrtf(total * (1.0f / 128.0f) + RMS_EPS);
    float xn = v * sc;
    xs[t] = xn;
    __syncthreads();

    float out;
    if (t < HALF) {
        float c = ct[s * HALF + t], sn = st[s * HALF + t];
        out = xn * c + xs[t + HALF] * sn;
    } else {
        int f = t - HALF;
        float c = ct[s * HALF + f], sn = st[s * HALF + f];
        out = xn * c - xs[f] * sn;
    }
    p[t] = out;
}

// ================= Flash attention fp32 (BM=BN=64, D=128, GQA causal) =================
#define ATT_SMEM_FLOATS (128 * 65 * 2 + 64 * 132 + 64 * 68)
#define ATT_SMEM_BYTES  (ATT_SMEM_FLOATS * 4)

__global__ __launch_bounds__(256) void attn_kernel(
    const float* __restrict__ qkv, float* __restrict__ y)
{
    extern __shared__ float sm[];
    float* Qt = sm;                       // [128][65]
    float* Kt = Qt + 128 * 65;            // [128][65]
    float* Vs = Kt + 128 * 65;            // [64][132]
    float* Pt = Vs + 64 * 132;            // [64][68]

    const int tid = threadIdx.x;
    const int tx = tid & 15;
    const int ty = tid >> 4;
    const int i0 = blockIdx.x * 64;
    const int bh = blockIdx.y;
    const int b = bh >> 4;
    const int h = bh & 15;
    const int kvh = h >> 2;

    const size_t rowbase = (size_t)b * SEQ * QKVW;
    const int kcol = DIMV + kvh * HD;
    const int vcol = DIMV + NKV * HD + kvh * HD;

    {
        int r0 = tid >> 5;
        int c4 = (tid & 31) * 4;
        for (int rr = r0; rr < 64; rr += 8) {
            const float* src = qkv + rowbase + (size_t)(i0 + rr) * QKVW + h * HD + c4;
            float4 v = *(const float4*)src;
            Qt[(c4 + 0) * 65 + rr] = v.x * ATT_SCALE;
            Qt[(c4 + 1) * 65 + rr] = v.y * ATT_SCALE;
            Qt[(c4 + 2) * 65 + rr] = v.z * ATT_SCALE;
            Qt[(c4 + 3) * 65 + rr] = v.w * ATT_SCALE;
        }
    }

    float m_i[4], l_i[4], o[4][2][4];
#pragma unroll
    for (int i = 0; i < 4; i++) {
        m_i[i] = -CUDART_INF_F;
        l_i[i] = 0.f;
#pragma unroll
        for (int q = 0; q < 2; q++)
#pragma unroll
            for (int u = 0; u < 4; u++) o[i][q][u] = 0.f;
    }

    for (int j0 = 0; j0 <= i0; j0 += 64) {
        __syncthreads();
        {
            int r0 = tid >> 5;
            int c4 = (tid & 31) * 4;
            for (int rr = r0; rr < 64; rr += 8) {
                const float* ks = qkv + rowbase + (size_t)(j0 + rr) * QKVW + kcol + c4;
                float4 kv4 = *(const float4*)ks;
                Kt[(c4 + 0) * 65 + rr] = kv4.x;
                Kt[(c4 + 1) * 65 + rr] = kv4.y;
                Kt[(c4 + 2) * 65 + rr] = kv4.z;
                Kt[(c4 + 3) * 65 + rr] = kv4.w;
                const float* vsrc = qkv + rowbase + (size_t)(j0 + rr) * QKVW + vcol + c4;
                *(float4*)&Vs[rr * 132 + c4] = *(const float4*)vsrc;
            }
        }
        __syncthreads();

        float scv[4][4];
#pragma unroll
        for (int i = 0; i < 4; i++)
#pragma unroll
            for (int u = 0; u < 4; u++) scv[i][u] = 0.f;

#pragma unroll 4
        for (int kk = 0; kk < 128; kk++) {
            const float* qrow = &Qt[kk * 65 + ty * 4];
            float qv[4] = {qrow[0], qrow[1], qrow[2], qrow[3]};
            const float* krow = &Kt[kk * 65];
            float kv[4] = {krow[tx * 2], krow[tx * 2 + 1], krow[32 + tx * 2], krow[33 + tx * 2]};
#pragma unroll
            for (int i = 0; i < 4; i++)
#pragma unroll
                for (int u = 0; u < 4; u++) scv[i][u] += qv[i] * kv[u];
        }

        if (j0 == i0) {
#pragma unroll
            for (int i = 0; i < 4; i++) {
                int rloc = ty * 4 + i;
#pragma unroll
                for (int u = 0; u < 4; u++) {
                    int cloc = ((u >> 1) << 5) + tx * 2 + (u & 1);
                    if (cloc > rloc) scv[i][u] = -CUDART_INF_F;
                }
            }
        }

#pragma unroll
        for (int i = 0; i < 4; i++) {
            float mt = fmaxf(fmaxf(scv[i][0], scv[i][1]), fmaxf(scv[i][2], scv[i][3]));
#pragma unroll
            for (int off = 8; off >= 1; off >>= 1)
                mt = fmaxf(mt, __shfl_xor_sync(0xffffffffu, mt, off));
            float mnew = fmaxf(m_i[i], mt);
            float alpha = expf(m_i[i] - mnew);
            m_i[i] = mnew;
            float p[4], rs = 0.f;
#pragma unroll
            for (int u = 0; u < 4; u++) { p[u] = expf(scv[i][u] - mnew); rs += p[u]; }
#pragma unroll
            for (int off = 8; off >= 1; off >>= 1)
                rs += __shfl_xor_sync(0xffffffffu, rs, off);
            l_i[i] = l_i[i] * alpha + rs;
#pragma unroll
            for (int q = 0; q < 2; q++)
#pragma unroll
                for (int u = 0; u < 4; u++) o[i][q][u] *= alpha;
#pragma unroll
            for (int u = 0; u < 4; u++) {
                int cloc = ((u >> 1) << 5) + tx * 2 + (u & 1);
                Pt[cloc * 68 + ty * 4 + i] = p[u];
            }
        }
        __syncthreads();

#pragma unroll 2
        for (int j = 0; j < 64; j++) {
            float4 pv = *(const float4*)&Pt[j * 68 + ty * 4];
            float4 v0 = *(const float4*)&Vs[j * 132 + tx * 4];
            float4 v1 = *(const float4*)&Vs[j * 132 + 64 + tx * 4];
            float pr[4] = {pv.x, pv.y, pv.z, pv.w};
            float va[2][4] = {{v0.x, v0.y, v0.z, v0.w}, {v1.x, v1.y, v1.z, v1.w}};
#pragma unroll
            for (int i = 0; i < 4; i++)
#pragma unroll
                for (int q = 0; q < 2; q++)
#pragma unroll
                    for (int u = 0; u < 4; u++) o[i][q][u] += pr[i] * va[q][u];
        }
    }

#pragma unroll
    for (int i = 0; i < 4; i++) {
        float inv = 1.0f / l_i[i];
        int srow = i0 + ty * 4 + i;
        float* dst = y + (size_t)(b * SEQ + srow) * DIMV + h * HD;
#pragma unroll
        for (int q = 0; q < 2; q++) {
            float4 v = make_float4(o[i][q][0] * inv, o[i][q][1] * inv,
                                   o[i][q][2] * inv, o[i][q][3] * inv);
            *(float4*)(dst + q * 64 + tx * 4) = v;
        }
    }
}

// ================= launch =================
extern "C" void kernel_launch(void* const* d_in, const int* in_sizes, int n_in,
                              void* d_out, int out_size)
{
    const float* x    = (const float*)d_in[0];
    const float* Wqkv = (const float*)d_in[1];
    const float* Wout = (const float*)d_in[2];
    float* out = (float*)d_out;

    float *qkv, *y, *ct, *st;
    cudaGetSymbolAddress((void**)&qkv, g_qkv);
    cudaGetSymbolAddress((void**)&y,   g_y);
    cudaGetSymbolAddress((void**)&ct,  g_cos);
    cudaGetSymbolAddress((void**)&st,  g_sin);

    // 1. RoPE tables
    rope_table_kernel<<<(SEQ * HALF + 255) / 256, 256>>>(ct, st);

    // 2. QKV projection: [8192,2048] @ [2048,3072]  (TF32 tensor cores)
    cudaFuncSetAttribute(gemm_tf32_kernel, cudaFuncAttributeMaxDynamicSharedMemorySize, GEMM_SMEM_BYTES);
    gemm_tf32_kernel<<<dim3(QKVW / BN, NTOK / BM), 256, GEMM_SMEM_BYTES>>>(x, Wqkv, qkv, NTOK, QKVW, DIMV);

    // 3. RMS-norm + RoPE on q and k heads (in place)
    rmsrope_kernel<<<dim3(NTOK, NHEAD + NKV), 128>>>(qkv, ct, st);

    // 4. causal GQA flash attention (fp32)
    cudaFuncSetAttribute(attn_kernel, cudaFuncAttributeMaxDynamicSharedMemorySize, ATT_SMEM_BYTES);
    attn_kernel<<<dim3(SEQ / 64, BATCH * NHEAD), 256, ATT_SMEM_BYTES>>>(qkv, y);

    // 5. output projection: [8192,2048] @ [2048,2048]  (TF32 tensor cores)
    gemm_tf32_kernel<<<dim3(DIMV / BN, NTOK / BM), 256, GEMM_SMEM_BYTES>>>(y, Wout, out, NTOK, DIMV, DIMV);
}

// round 3
// speedup vs baseline: 2.7665x; 1.6751x over previous
#include <cuda_runtime.h>
#include <math.h>
#include <math_constants.h>

// ---------------- problem constants ----------------
#define DIMV   2048
#define SEQ    2048
#define BATCH  4
#define NHEAD  16
#define NKV    4
#define HD     128
#define HALF   64
#define QKVW   (DIMV + 2 * NKV * HD)   // 3072
#define NTOK   (BATCH * SEQ)           // 8192
#define RMS_EPS 1.1920929e-07f
#define ATT_SCALE 0.08838834764831845f // 1/sqrt(128)

// ---------------- scratch (static device globals; no allocation) ----------------
__device__ float g_qkv[(size_t)NTOK * QKVW];   // 96 MB
__device__ float g_y[(size_t)NTOK * DIMV];     // 64 MB
__device__ float g_cos[SEQ * HALF];
__device__ float g_sin[SEQ * HALF];

// ================= RoPE table (double-precision angles) =================
__global__ void rope_table_kernel(float* __restrict__ ct, float* __restrict__ st) {
    int idx = blockIdx.x * blockDim.x + threadIdx.x;
    if (idx >= SEQ * HALF) return;
    int s = idx >> 6;
    int f = idx & 63;
    double inv = pow(10000.0, -((double)(2 * f)) / 128.0);
    double th = (double)s * inv;
    ct[idx] = (float)cos(th);
    st[idx] = (float)sin(th);
}

// ---------------- TF32 helpers ----------------
__device__ __forceinline__ unsigned f2tf32(float f) {
    unsigned r;
    asm("cvt.rna.tf32.f32 %0, %1;" : "=r"(r) : "f"(f));
    return r;
}
__device__ __forceinline__ float f2tf32f(float f) {
    unsigned r = f2tf32(f);
    return __uint_as_float(r);
}

__device__ __forceinline__ void cp_async16(void* dst_smem, const void* src_gmem) {
    unsigned d = (unsigned)__cvta_generic_to_shared(dst_smem);
    asm volatile("cp.async.cg.shared.global [%0], [%1], 16;\n" :: "r"(d), "l"(src_gmem));
}
#define CP_COMMIT asm volatile("cp.async.commit_group;\n" ::: "memory")
#define CP_WAIT2  asm volatile("cp.async.wait_group 2;\n" ::: "memory")

__device__ __forceinline__ void mma_tf32(float* c, const unsigned* a, const unsigned* b) {
    asm volatile(
        "mma.sync.aligned.m16n8k8.row.col.f32.tf32.tf32.f32 "
        "{%0,%1,%2,%3}, {%4,%5,%6,%7}, {%8,%9}, {%0,%1,%2,%3};\n"
        : "+f"(c[0]), "+f"(c[1]), "+f"(c[2]), "+f"(c[3])
        : "r"(a[0]), "r"(a[1]), "r"(a[2]), "r"(a[3]), "r"(b[0]), "r"(b[1]));
}

// ======================================================================
// TF32 tensor-core GEMM: C[M,N] = A[M,K] @ B[K,N], row-major, fp32 in/out
// ======================================================================
#define BM 128
#define BN 256
#define BK 16
#define STAGES 4
#define A_STRIDE 20
#define B_STRIDE 264
#define A_FLOATS (BM * A_STRIDE)
#define B_FLOATS (BK * B_STRIDE)
#define STAGE_FLOATS (A_FLOATS + B_FLOATS)
#define GEMM_SMEM_BYTES (STAGES * STAGE_FLOATS * 4)

__global__ __launch_bounds__(256, 1) void gemm_tf32_kernel(
    const float* __restrict__ A, const float* __restrict__ B, float* __restrict__ C,
    int M, int N, int K)
{
    extern __shared__ float sm[];
    const int tid = threadIdx.x;
    const int warp = tid >> 5;
    const int lane = tid & 31;
    const int grp = lane >> 2;
    const int tig = lane & 3;
    const int wm = warp >> 2;
    const int wn = warp & 3;
    const int row0 = blockIdx.y * BM;
    const int col0 = blockIdx.x * BN;

    const int NIT = K / BK;

    auto issue_load = [&](int buf, int k0) {
        float* sA = sm + buf * STAGE_FLOATS;
        float* sB = sA + A_FLOATS;
#pragma unroll
        for (int rep = 0; rep < 2; rep++) {
            int idx = tid + rep * 256;
            int m = idx >> 2, kq = (idx & 3) * 4;
            cp_async16(sA + m * A_STRIDE + kq,
                       A + (size_t)(row0 + m) * K + k0 + kq);
        }
#pragma unroll
        for (int rep = 0; rep < 4; rep++) {
            int idx = tid + rep * 256;
            int k = idx >> 6, nq = (idx & 63) * 4;
            cp_async16(sB + k * B_STRIDE + nq,
                       B + (size_t)(k0 + k) * N + col0 + nq);
        }
    };

    float acc[4][8][4];
#pragma unroll
    for (int mt = 0; mt < 4; mt++)
#pragma unroll
        for (int nt = 0; nt < 8; nt++)
#pragma unroll
            for (int r = 0; r < 4; r++) acc[mt][nt][r] = 0.f;

#pragma unroll
    for (int s = 0; s < STAGES - 1; s++) {
        issue_load(s, s * BK);
        CP_COMMIT;
    }

    for (int it = 0; it < NIT; it++) {
        CP_WAIT2;
        __syncthreads();

        if (it + STAGES - 1 < NIT)
            issue_load((it + STAGES - 1) & (STAGES - 1), (it + STAGES - 1) * BK);
        CP_COMMIT;

        const float* sA = sm + (it & (STAGES - 1)) * STAGE_FLOATS;
        const float* sB = sA + A_FLOATS;

#pragma unroll
        for (int ks = 0; ks < 2; ks++) {
            unsigned af[4][4], bf[8][2];
            const int kk = ks * 8 + tig;
#pragma unroll
            for (int mt = 0; mt < 4; mt++) {
                const float* ap = sA + (wm * 64 + mt * 16 + grp) * A_STRIDE + kk;
                af[mt][0] = f2tf32(ap[0]);
                af[mt][1] = f2tf32(ap[8 * A_STRIDE]);
                af[mt][2] = f2tf32(ap[4]);
                af[mt][3] = f2tf32(ap[8 * A_STRIDE + 4]);
            }
#pragma unroll
            for (int nt = 0; nt < 8; nt++) {
                const float* bp = sB + kk * B_STRIDE + wn * 64 + nt * 8 + grp;
                bf[nt][0] = f2tf32(bp[0]);
                bf[nt][1] = f2tf32(bp[4 * B_STRIDE]);
            }
#pragma unroll
            for (int mt = 0; mt < 4; mt++)
#pragma unroll
                for (int nt = 0; nt < 8; nt++)
                    mma_tf32(acc[mt][nt], af[mt], bf[nt]);
        }
        __syncthreads();
    }

#pragma unroll
    for (int mt = 0; mt < 4; mt++) {
        int row = row0 + wm * 64 + mt * 16 + grp;
#pragma unroll
        for (int nt = 0; nt < 8; nt++) {
            int col = col0 + wn * 64 + nt * 8 + tig * 2;
            float* c0 = C + (size_t)row * N + col;
            float* c1 = C + (size_t)(row + 8) * N + col;
            *(float2*)c0 = make_float2(acc[mt][nt][0], acc[mt][nt][1]);
            *(float2*)c1 = make_float2(acc[mt][nt][2], acc[mt][nt][3]);
        }
    }
}

// ================= RMS-norm + RoPE, in place over g_qkv =================
__global__ __launch_bounds__(128) void rmsrope_kernel(
    float* __restrict__ qkv, const float* __restrict__ ct, const float* __restrict__ st)
{
    const int row = blockIdx.x;
    const int hh = blockIdx.y;
    const int s = row & (SEQ - 1);
    const int col = (hh < NHEAD) ? hh * HD : DIMV + (hh - NHEAD) * HD;
    float* p = qkv + (size_t)row * QKVW + col;
    const int t = threadIdx.x;

    float v = p[t];
    float sq = v * v;
#pragma unroll
    for (int off = 16; off; off >>= 1) sq += __shfl_xor_sync(0xffffffffu, sq, off);

    __shared__ float red[4];
    __shared__ float xs[128];
    if ((t & 31) == 0) red[t >> 5] = sq;
    __syncthreads();
    float total = red[0] + red[1] + red[2] + red[3];
    float sc = rsqrtf(total * (1.0f / 128.0f) + RMS_EPS);
    float xn = v * sc;
    xs[t] = xn;
    __syncthreads();

    float out;
    if (t < HALF) {
        float c = ct[s * HALF + t], sn = st[s * HALF + t];
        out = xn * c + xs[t + HALF] * sn;
    } else {
        int f = t - HALF;
        float c = ct[s * HALF + f], sn = st[s * HALF + f];
        out = xn * c - xs[f] * sn;
    }
    p[t] = out;
}

// ======================================================================
// TF32 tensor-core flash attention (BM=128 Q rows, BN=64 keys, D=128, GQA causal)
// 8 warps; warp w owns Q rows [w*16, w*16+16). Q frags register-resident.
// smem: Ks[64][132] | Vs[64][132] | Ps[8 warps][16][68]; Q staging aliases Ks+Vs.
// ======================================================================
#define AT_STRIDE 132
#define AT_PS     68
#define AT_KFLOATS (64 * AT_STRIDE)                 // 8448
#define AT_SMEM_FLOATS (2 * AT_KFLOATS + 8 * 16 * AT_PS)  // 25600
#define AT_SMEM_BYTES (AT_SMEM_FLOATS * 4)          // 102400

__global__ __launch_bounds__(256, 1) void attn_mma_kernel(
    const float* __restrict__ qkv, float* __restrict__ y)
{
    extern __shared__ float sm[];
    float* Ks = sm;                       // [64][132] (tf32-rounded floats)
    float* Vs = sm + AT_KFLOATS;          // [64][132]
    float* Ps = sm + 2 * AT_KFLOATS;      // per warp [16][68]
    float* Qstage = sm;                   // aliases Ks+Vs: [128][132]

    const int tid = threadIdx.x;
    const int warp = tid >> 5;
    const int lane = tid & 31;
    const int grp = lane >> 2;
    const int tig = lane & 3;

    const int i0 = blockIdx.x * 128;
    const int bh = blockIdx.y;
    const int b = bh >> 4;
    const int h = bh & 15;
    const int kvh = h >> 2;

    const size_t rowbase = (size_t)b * SEQ * QKVW;
    const int kcol = DIMV + kvh * HD;
    const int vcol = DIMV + NKV * HD + kvh * HD;

    // ---- stage Q (scaled) into smem, coalesced ----
    for (int idx = tid; idx < 128 * 32; idx += 256) {
        int row = idx >> 5;
        int c4 = (idx & 31) * 4;
        float4 v = *(const float4*)(qkv + rowbase + (size_t)(i0 + row) * QKVW + h * HD + c4);
        float* d = Qstage + row * AT_STRIDE + c4;
        d[0] = v.x * ATT_SCALE; d[1] = v.y * ATT_SCALE;
        d[2] = v.z * ATT_SCALE; d[3] = v.w * ATT_SCALE;
    }
    __syncthreads();

    // ---- extract Q fragments into registers (16 k-steps) ----
    unsigned qf[16][4];
    {
        const float* qp = Qstage + (warp * 16 + grp) * AT_STRIDE + tig;
#pragma unroll
        for (int ks = 0; ks < 16; ks++) {
            qf[ks][0] = f2tf32(qp[ks * 8]);
            qf[ks][1] = f2tf32(qp[ks * 8 + 8 * AT_STRIDE]);
            qf[ks][2] = f2tf32(qp[ks * 8 + 4]);
            qf[ks][3] = f2tf32(qp[ks * 8 + 4 + 8 * AT_STRIDE]);
        }
    }

    float of[16][4];
#pragma unroll
    for (int nf = 0; nf < 16; nf++)
#pragma unroll
        for (int r = 0; r < 4; r++) of[nf][r] = 0.f;
    float m0 = -CUDART_INF_F, m1 = -CUDART_INF_F, l0 = 0.f, l1 = 0.f;

    const int qi0 = i0 + warp * 16 + grp;
    const int qi1 = qi0 + 8;
    float* Pw = Ps + warp * (16 * AT_PS);

    for (int j0 = 0; j0 <= i0 + 127; j0 += 64) {
        __syncthreads();   // prior iter's Ks/Vs reads done (and Q staging on iter 0)

        // ---- load K/V tile (tf32-rounded at store) ----
        for (int idx = tid; idx < 64 * 32; idx += 256) {
            int row = idx >> 5;
            int c4 = (idx & 31) * 4;
            const float* ksrc = qkv + rowbase + (size_t)(j0 + row) * QKVW + kcol + c4;
            float4 kv = *(const float4*)ksrc;
            float* kd = Ks + row * AT_STRIDE + c4;
            kd[0] = f2tf32f(kv.x); kd[1] = f2tf32f(kv.y);
            kd[2] = f2tf32f(kv.z); kd[3] = f2tf32f(kv.w);
            const float* vsrc = qkv + rowbase + (size_t)(j0 + row) * QKVW + vcol + c4;
            float4 vv = *(const float4*)vsrc;
            float* vd = Vs + row * AT_STRIDE + c4;
            vd[0] = f2tf32f(vv.x); vd[1] = f2tf32f(vv.y);
            vd[2] = f2tf32f(vv.z); vd[3] = f2tf32f(vv.w);
        }
        __syncthreads();

        // ---- S = Q K^T : 8 n-frags of m16n8 ----
        float sacc[8][4];
#pragma unroll
        for (int nf = 0; nf < 8; nf++)
#pragma unroll
            for (int r = 0; r < 4; r++) sacc[nf][r] = 0.f;

#pragma unroll
        for (int ks = 0; ks < 16; ks++) {
            unsigned bf[8][2];
            const int d = ks * 8 + tig;
#pragma unroll
            for (int nf = 0; nf < 8; nf++) {
                const float* kp = Ks + (nf * 8 + grp) * AT_STRIDE + d;
                bf[nf][0] = __float_as_uint(kp[0]);
                bf[nf][1] = __float_as_uint(kp[4]);
            }
#pragma unroll
            for (int nf = 0; nf < 8; nf++)
                mma_tf32(sacc[nf], qf[ks], bf[nf]);
        }

        // ---- causal mask (last two tiles only) ----
        if (j0 + 63 > i0) {
#pragma unroll
            for (int nf = 0; nf < 8; nf++) {
                int key = j0 + nf * 8 + 2 * tig;
                if (key     > qi0) sacc[nf][0] = -CUDART_INF_F;
                if (key + 1 > qi0) sacc[nf][1] = -CUDART_INF_F;
                if (key     > qi1) sacc[nf][2] = -CUDART_INF_F;
                if (key + 1 > qi1) sacc[nf][3] = -CUDART_INF_F;
            }
        }

        // ---- online softmax (rows qi0, qi1 shared by 4 lanes of same grp) ----
        float mx0 = -CUDART_INF_F, mx1 = -CUDART_INF_F;
#pragma unroll
        for (int nf = 0; nf < 8; nf++) {
            mx0 = fmaxf(mx0, fmaxf(sacc[nf][0], sacc[nf][1]));
            mx1 = fmaxf(mx1, fmaxf(sacc[nf][2], sacc[nf][3]));
        }
        mx0 = fmaxf(mx0, __shfl_xor_sync(0xffffffffu, mx0, 1));
        mx0 = fmaxf(mx0, __shfl_xor_sync(0xffffffffu, mx0, 2));
        mx1 = fmaxf(mx1, __shfl_xor_sync(0xffffffffu, mx1, 1));
        mx1 = fmaxf(mx1, __shfl_xor_sync(0xffffffffu, mx1, 2));

        float m0n = fmaxf(m0, mx0);
        float m1n = fmaxf(m1, mx1);
        float alpha0 = __expf(m0 - m0n);
        float alpha1 = __expf(m1 - m1n);
        m0 = m0n; m1 = m1n;

        float rs0 = 0.f, rs1 = 0.f;
#pragma unroll
        for (int nf = 0; nf < 8; nf++) {
            float p0 = __expf(sacc[nf][0] - m0);
            float p1 = __expf(sacc[nf][1] - m0);
            float p2 = __expf(sacc[nf][2] - m1);
            float p3 = __expf(sacc[nf][3] - m1);
            rs0 += p0 + p1;
            rs1 += p2 + p3;
            *(float2*)&Pw[grp * AT_PS + nf * 8 + 2 * tig] =
                make_float2(f2tf32f(p0), f2tf32f(p1));
            *(float2*)&Pw[(grp + 8) * AT_PS + nf * 8 + 2 * tig] =
                make_float2(f2tf32f(p2), f2tf32f(p3));
        }
        rs0 += __shfl_xor_sync(0xffffffffu, rs0, 1);
        rs0 += __shfl_xor_sync(0xffffffffu, rs0, 2);
        rs1 += __shfl_xor_sync(0xffffffffu, rs1, 1);
        rs1 += __shfl_xor_sync(0xffffffffu, rs1, 2);
        l0 = l0 * alpha0 + rs0;
        l1 = l1 * alpha1 + rs1;

#pragma unroll
        for (int nf = 0; nf < 16; nf++) {
            of[nf][0] *= alpha0; of[nf][1] *= alpha0;
            of[nf][2] *= alpha1; of[nf][3] *= alpha1;
        }
        __syncwarp();

        // ---- O += P V : reduction over 64 keys (8 k-steps) ----
#pragma unroll
        for (int ks = 0; ks < 8; ks++) {
            unsigned af[4];
            af[0] = __float_as_uint(Pw[grp * AT_PS + ks * 8 + tig]);
            af[1] = __float_as_uint(Pw[(grp + 8) * AT_PS + ks * 8 + tig]);
            af[2] = __float_as_uint(Pw[grp * AT_PS + ks * 8 + tig + 4]);
            af[3] = __float_as_uint(Pw[(grp + 8) * AT_PS + ks * 8 + tig + 4]);
            const float* vrow0 = Vs + (ks * 8 + tig) * AT_STRIDE;
            const float* vrow1 = Vs + (ks * 8 + tig + 4) * AT_STRIDE;
#pragma unroll
            for (int nf = 0; nf < 16; nf++) {
                unsigned bf[2];
                bf[0] = __float_as_uint(vrow0[nf * 8 + grp]);
                bf[1] = __float_as_uint(vrow1[nf * 8 + grp]);
                mma_tf32(of[nf], af, bf);
            }
        }
        __syncwarp();
    }

    // ---- epilogue ----
    float inv0 = 1.0f / l0, inv1 = 1.0f / l1;
    int r0 = i0 + warp * 16 + grp;
    float* dst0 = y + (size_t)(b * SEQ + r0) * DIMV + h * HD;
    float* dst1 = y + (size_t)(b * SEQ + r0 + 8) * DIMV + h * HD;
#pragma unroll
    for (int nf = 0; nf < 16; nf++) {
        *(float2*)(dst0 + nf * 8 + 2 * tig) = make_float2(of[nf][0] * inv0, of[nf][1] * inv0);
        *(float2*)(dst1 + nf * 8 + 2 * tig) = make_float2(of[nf][2] * inv1, of[nf][3] * inv1);
    }
}

// ================= launch =================
extern "C" void kernel_launch(void* const* d_in, const int* in_sizes, int n_in,
                              void* d_out, int out_size)
{
    const float* x    = (const float*)d_in[0];
    const float* Wqkv = (const float*)d_in[1];
    const float* Wout = (const float*)d_in[2];
    float* out = (float*)d_out;

    float *qkv, *y, *ct, *st;
    cudaGetSymbolAddress((void**)&qkv, g_qkv);
    cudaGetSymbolAddress((void**)&y,   g_y);
    cudaGetSymbolAddress((void**)&ct,  g_cos);
    cudaGetSymbolAddress((void**)&st,  g_sin);

    // 1. RoPE tables
    rope_table_kernel<<<(SEQ * HALF + 255) / 256, 256>>>(ct, st);

    // 2. QKV projection (TF32 tensor cores)
    cudaFuncSetAttribute(gemm_tf32_kernel, cudaFuncAttributeMaxDynamicSharedMemorySize, GEMM_SMEM_BYTES);
    gemm_tf32_kernel<<<dim3(QKVW / BN, NTOK / BM), 256, GEMM_SMEM_BYTES>>>(x, Wqkv, qkv, NTOK, QKVW, DIMV);

    // 3. RMS-norm + RoPE
    rmsrope_kernel<<<dim3(NTOK, NHEAD + NKV), 128>>>(qkv, ct, st);

    // 4. causal GQA flash attention (TF32 tensor cores)
    cudaFuncSetAttribute(attn_mma_kernel, cudaFuncAttributeMaxDynamicSharedMemorySize, AT_SMEM_BYTES);
    attn_mma_kernel<<<dim3(SEQ / 128, BATCH * NHEAD), 256, AT_SMEM_BYTES>>>(qkv, y);

    // 5. output projection (TF32 tensor cores)
    gemm_tf32_kernel<<<dim3(DIMV / BN, NTOK / BM), 256, GEMM_SMEM_BYTES>>>(y, Wout, out, NTOK, DIMV, DIMV);
}

// round 5
// speedup vs baseline: 2.8853x; 1.0429x over previous
#include <cuda_runtime.h>
#include <math.h>
#include <math_constants.h>
#include <cstdint>

// ---------------- problem constants ----------------
#define DIMV   2048
#define SEQ    2048
#define BATCH  4
#define NHEAD  16
#define NKV    4
#define HD     128
#define HALF   64
#define QKVW   (DIMV + 2 * NKV * HD)   // 3072
#define NTOK   (BATCH * SEQ)           // 8192
#define RMS_EPS 1.1920929e-07f
#define ATT_SCALE 0.08838834764831845f // 1/sqrt(128)

// ---------------- scratch (static device globals; no allocation) ----------------
__device__ float g_qkv[(size_t)NTOK * QKVW];    // 96 MB
__device__ float g_y[(size_t)NTOK * DIMV];      // 64 MB (tf32-rounded attention out)
__device__ float g_xr[(size_t)NTOK * DIMV];     // 64 MB (tf32-rounded x)
__device__ float g_wqr[(size_t)DIMV * QKVW];    // 24 MB (W_qkv tf32-rounded, row-major)
__device__ float g_wor[(size_t)DIMV * DIMV];    // 16 MB (W_out tf32-rounded, row-major)
__device__ float g_cos[SEQ * HALF];
__device__ float g_sin[SEQ * HALF];

// ---------------- helpers ----------------
__device__ __forceinline__ unsigned f2tf32(float f) {
    unsigned r;
    asm("cvt.rna.tf32.f32 %0, %1;" : "=r"(r) : "f"(f));
    return r;
}
__device__ __forceinline__ float f2tf32f(float f) { return __uint_as_float(f2tf32(f)); }

__device__ __forceinline__ void cp_async16(void* dst_smem, const void* src_gmem) {
    unsigned d = (unsigned)__cvta_generic_to_shared(dst_smem);
    asm volatile("cp.async.cg.shared.global [%0], [%1], 16;\n" :: "r"(d), "l"(src_gmem));
}
#define CP_COMMIT asm volatile("cp.async.commit_group;\n" ::: "memory")
#define CP_WAIT1  asm volatile("cp.async.wait_group 1;\n" ::: "memory")
#define CP_WAIT2  asm volatile("cp.async.wait_group 2;\n" ::: "memory")

__device__ __forceinline__ void mma_tf32(float* c, const unsigned* a, const unsigned* b) {
    asm volatile(
        "mma.sync.aligned.m16n8k8.row.col.f32.tf32.tf32.f32 "
        "{%0,%1,%2,%3}, {%4,%5,%6,%7}, {%8,%9}, {%0,%1,%2,%3};\n"
        : "+f"(c[0]), "+f"(c[1]), "+f"(c[2]), "+f"(c[3])
        : "r"(a[0]), "r"(a[1]), "r"(a[2]), "r"(a[3]), "r"(b[0]), "r"(b[1]));
}

// ================= RoPE table (double-precision angles) =================
__global__ void rope_table_kernel(float* __restrict__ ct, float* __restrict__ st) {
    int idx = blockIdx.x * blockDim.x + threadIdx.x;
    if (idx >= SEQ * HALF) return;
    int s = idx >> 6;
    int f = idx & 63;
    double inv = pow(10000.0, -((double)(2 * f)) / 128.0);
    double th = (double)s * inv;
    ct[idx] = (float)cos(th);
    st[idx] = (float)sin(th);
}

// ================= tf32-round copy =================
__global__ __launch_bounds__(256) void round_copy_kernel(
    const float* __restrict__ src, float* __restrict__ dst, size_t n4)
{
    size_t i = (size_t)blockIdx.x * blockDim.x + threadIdx.x;
    if (i >= n4) return;
    float4 v = ((const float4*)src)[i];
    v.x = f2tf32f(v.x); v.y = f2tf32f(v.y); v.z = f2tf32f(v.z); v.w = f2tf32f(v.w);
    ((float4*)dst)[i] = v;
}

// ======================================================================
// TF32 tensor-core GEMM: C[M,N] = A[M,K] @ B[K,N], row-major.
// OPERANDS MUST BE PRE-ROUNDED TO TF32 (no cvt in hot loop).
// CTA tile 128x256, BK=16, 4-stage cp.async, 8 warps, warp tile 64x64.
// ======================================================================
#define BM 128
#define BN 256
#define BK 16
#define STAGES 4
#define A_STRIDE 20
#define B_STRIDE 264
#define A_FLOATS (BM * A_STRIDE)
#define B_FLOATS (BK * B_STRIDE)
#define STAGE_FLOATS (A_FLOATS + B_FLOATS)
#define GEMM_SMEM_BYTES (STAGES * STAGE_FLOATS * 4)

__global__ __launch_bounds__(256, 1) void gemm_tf32_kernel(
    const float* __restrict__ A, const float* __restrict__ B, float* __restrict__ C,
    int M, int N, int K)
{
    extern __shared__ float sm[];
    const int tid = threadIdx.x;
    const int warp = tid >> 5;
    const int lane = tid & 31;
    const int grp = lane >> 2;
    const int tig = lane & 3;
    const int wm = warp >> 2;
    const int wn = warp & 3;
    const int row0 = blockIdx.y * BM;
    const int col0 = blockIdx.x * BN;

    const int NIT = K / BK;

    auto issue_load = [&](int buf, int k0) {
        float* sA = sm + buf * STAGE_FLOATS;
        float* sB = sA + A_FLOATS;
#pragma unroll
        for (int rep = 0; rep < 2; rep++) {
            int idx = tid + rep * 256;
            int m = idx >> 2, kq = (idx & 3) * 4;
            cp_async16(sA + m * A_STRIDE + kq,
                       A + (size_t)(row0 + m) * K + k0 + kq);
        }
#pragma unroll
        for (int rep = 0; rep < 4; rep++) {
            int idx = tid + rep * 256;
            int k = idx >> 6, nq = (idx & 63) * 4;
            cp_async16(sB + k * B_STRIDE + nq,
                       B + (size_t)(k0 + k) * N + col0 + nq);
        }
    };

    float acc[4][8][4];
#pragma unroll
    for (int mt = 0; mt < 4; mt++)
#pragma unroll
        for (int nt = 0; nt < 8; nt++)
#pragma unroll
            for (int r = 0; r < 4; r++) acc[mt][nt][r] = 0.f;

#pragma unroll
    for (int s = 0; s < STAGES - 1; s++) {
        issue_load(s, s * BK);
        CP_COMMIT;
    }

    for (int it = 0; it < NIT; it++) {
        CP_WAIT2;
        __syncthreads();

        if (it + STAGES - 1 < NIT)
            issue_load((it + STAGES - 1) & (STAGES - 1), (it + STAGES - 1) * BK);
        CP_COMMIT;

        const float* sA = sm + (it & (STAGES - 1)) * STAGE_FLOATS;
        const float* sB = sA + A_FLOATS;

#pragma unroll
        for (int ks = 0; ks < 2; ks++) {
            unsigned af[4][4], bf[8][2];
            const int kk = ks * 8 + tig;
#pragma unroll
            for (int mt = 0; mt < 4; mt++) {
                const float* ap = sA + (wm * 64 + mt * 16 + grp) * A_STRIDE + kk;
                af[mt][0] = __float_as_uint(ap[0]);
                af[mt][1] = __float_as_uint(ap[8 * A_STRIDE]);
                af[mt][2] = __float_as_uint(ap[4]);
                af[mt][3] = __float_as_uint(ap[8 * A_STRIDE + 4]);
            }
#pragma unroll
            for (int nt = 0; nt < 8; nt++) {
                const float* bp = sB + kk * B_STRIDE + wn * 64 + nt * 8 + grp;
                bf[nt][0] = __float_as_uint(bp[0]);
                bf[nt][1] = __float_as_uint(bp[4 * B_STRIDE]);
            }
#pragma unroll
            for (int mt = 0; mt < 4; mt++)
#pragma unroll
                for (int nt = 0; nt < 8; nt++)
                    mma_tf32(acc[mt][nt], af[mt], bf[nt]);
        }
        __syncthreads();
    }

#pragma unroll
    for (int mt = 0; mt < 4; mt++) {
        int row = row0 + wm * 64 + mt * 16 + grp;
#pragma unroll
        for (int nt = 0; nt < 8; nt++) {
            int col = col0 + wn * 64 + nt * 8 + tig * 2;
            float* c0 = C + (size_t)row * N + col;
            float* c1 = C + (size_t)(row + 8) * N + col;
            *(float2*)c0 = make_float2(acc[mt][nt][0], acc[mt][nt][1]);
            *(float2*)c1 = make_float2(acc[mt][nt][2], acc[mt][nt][3]);
        }
    }
}

// ================= RMS-norm + RoPE (+ tf32 rounding), in place over g_qkv =================
// grid (NTOK, 24): hh 0..15 q heads (norm+rope+round), 16..19 k heads (norm+rope+round),
//                  20..23 v heads (round only). 128 threads/block.
__global__ __launch_bounds__(128) void rmsrope_kernel(
    float* __restrict__ qkv, const float* __restrict__ ct, const float* __restrict__ st)
{
    const int row = blockIdx.x;
    const int hh = blockIdx.y;
    const int s = row & (SEQ - 1);
    const int t = threadIdx.x;

    if (hh >= NHEAD + NKV) {  // V heads: tf32-round only
        const int col = DIMV + NKV * HD + (hh - NHEAD - NKV) * HD;
        float* p = qkv + (size_t)row * QKVW + col;
        p[t] = f2tf32f(p[t]);
        return;
    }

    const int col = (hh < NHEAD) ? hh * HD : DIMV + (hh - NHEAD) * HD;
    float* p = qkv + (size_t)row * QKVW + col;

    float v = p[t];
    float sq = v * v;
#pragma unroll
    for (int off = 16; off; off >>= 1) sq += __shfl_xor_sync(0xffffffffu, sq, off);

    __shared__ float red[4];
    __shared__ float xs[128];
    if ((t & 31) == 0) red[t >> 5] = sq;
    __syncthreads();
    float total = red[0] + red[1] + red[2] + red[3];
    float sc = rsqrtf(total * (1.0f / 128.0f) + RMS_EPS);
    float xn = v * sc;
    xs[t] = xn;
    __syncthreads();

    float out;
    if (t < HALF) {
        float c = ct[s * HALF + t], sn = st[s * HALF + t];
        out = xn * c + xs[t + HALF] * sn;
    } else {
        int f = t - HALF;
        float c = ct[s * HALF + f], sn = st[s * HALF + f];
        out = xn * c - xs[f] * sn;
    }
    p[t] = f2tf32f(out);
}

// ======================================================================
// TF32 mma.sync flash attention, cp.async double-buffered K/V.
// BM=128 Q rows/CTA, BN=64 keys/iter, D=128, GQA causal, 8 warps.
// smem: KV stages [2] x (Ks[64][132] + Vs[64][132]) | Ps[8][16][68]
// Q staging aliases the KV double-buffer region.
// Scale folded into softmax exponent (Q stays exactly tf32).
// ======================================================================
#define AT_STRIDE 132
#define AT_PS     68
#define AT_TILE   (64 * AT_STRIDE)                 // 8448 floats (one K or V tile)
#define AT_KV_FLOATS (4 * AT_TILE)                  // 33792 (2 stages x K,V)
#define AT_SMEM_FLOATS (AT_KV_FLOATS + 8 * 16 * AT_PS)  // 42496
#define AT_SMEM_BYTES (AT_SMEM_FLOATS * 4)          // 169984

__global__ __launch_bounds__(256, 1) void attn_mma_kernel(
    const float* __restrict__ qkv, float* __restrict__ y)
{
    extern __shared__ float sm[];
    // stage s: Ks at sm + s*2*AT_TILE, Vs at sm + s*2*AT_TILE + AT_TILE
    float* Ps = sm + AT_KV_FLOATS;
    float* Qstage = sm;                   // aliases KV buffers during prologue

    const int tid = threadIdx.x;
    const int warp = tid >> 5;
    const int lane = tid & 31;
    const int grp = lane >> 2;
    const int tig = lane & 3;

    // reversed mapping: heavy (large i0) tiles first
    const int i0 = (gridDim.x - 1 - blockIdx.x) * 128;
    const int bh = blockIdx.y;
    const int b = bh >> 4;
    const int h = bh & 15;
    const int kvh = h >> 2;

    const size_t rowbase = (size_t)b * SEQ * QKVW;
    const int kcol = DIMV + kvh * HD;
    const int vcol = DIMV + NKV * HD + kvh * HD;

    // ---- stage Q into smem (already tf32-rounded, unscaled) ----
    for (int idx = tid; idx < 128 * 32; idx += 256) {
        int row = idx >> 5;
        int c4 = (idx & 31) * 4;
        float4 v = *(const float4*)(qkv + rowbase + (size_t)(i0 + row) * QKVW + h * HD + c4);
        *(float4*)(Qstage + row * AT_STRIDE + c4) = v;
    }
    __syncthreads();

    // ---- extract Q fragments ----
    unsigned qf[16][4];
    {
        const float* qp = Qstage + (warp * 16 + grp) * AT_STRIDE + tig;
#pragma unroll
        for (int ks = 0; ks < 16; ks++) {
            qf[ks][0] = __float_as_uint(qp[ks * 8]);
            qf[ks][1] = __float_as_uint(qp[ks * 8 + 8 * AT_STRIDE]);
            qf[ks][2] = __float_as_uint(qp[ks * 8 + 4]);
            qf[ks][3] = __float_as_uint(qp[ks * 8 + 4 + 8 * AT_STRIDE]);
        }
    }
    __syncthreads();   // everyone done reading Qstage; KV buffers may be overwritten

    // ---- cp.async loader for one K/V tile into stage buf ----
    auto issue_kv = [&](int buf, int j0) {
        float* Ks = sm + buf * 2 * AT_TILE;
        float* Vs = Ks + AT_TILE;
#pragma unroll
        for (int rep = 0; rep < 8; rep++) {
            int idx = tid + rep * 256;            // 0..2047
            int row = idx >> 5;
            int c4 = (idx & 31) * 4;
            const float* krow = qkv + rowbase + (size_t)(j0 + row) * QKVW;
            cp_async16(Ks + row * AT_STRIDE + c4, krow + kcol + c4);
            cp_async16(Vs + row * AT_STRIDE + c4, krow + vcol + c4);
        }
    };

    float of[16][4];
#pragma unroll
    for (int nf = 0; nf < 16; nf++)
#pragma unroll
        for (int r = 0; r < 4; r++) of[nf][r] = 0.f;
    float m0 = -CUDART_INF_F, m1 = -CUDART_INF_F, l0 = 0.f, l1 = 0.f;

    const int qi0 = i0 + warp * 16 + grp;
    const int qi1 = qi0 + 8;
    float* Pw = Ps + warp * (16 * AT_PS);

    const int NIT = (i0 + 128) / 64;

    // prologue: prefetch tile 0
    issue_kv(0, 0);
    CP_COMMIT;

    for (int it = 0; it < NIT; it++) {
        const int j0 = it * 64;
        const int buf = it & 1;

        // prefetch next tile into the other buffer (safe: previous iter's
        // compute on it finished before the closing __syncthreads below)
        if (it + 1 < NIT) issue_kv(buf ^ 1, j0 + 64);
        CP_COMMIT;
        CP_WAIT1;          // current buf complete (only the newest group may lag)
        __syncthreads();

        const float* Ks = sm + buf * 2 * AT_TILE;
        const float* Vs = Ks + AT_TILE;

        // ---- S = Q K^T ----
        float sacc[8][4];
#pragma unroll
        for (int nf = 0; nf < 8; nf++)
#pragma unroll
            for (int r = 0; r < 4; r++) sacc[nf][r] = 0.f;

#pragma unroll
        for (int ks = 0; ks < 16; ks++) {
            unsigned bf[8][2];
            const int d = ks * 8 + tig;
#pragma unroll
            for (int nf = 0; nf < 8; nf++) {
                const float* kp = Ks + (nf * 8 + grp) * AT_STRIDE + d;
                bf[nf][0] = __float_as_uint(kp[0]);
                bf[nf][1] = __float_as_uint(kp[4]);
            }
#pragma unroll
            for (int nf = 0; nf < 8; nf++)
                mma_tf32(sacc[nf], qf[ks], bf[nf]);
        }

        // ---- causal mask ----
        if (j0 + 63 > i0) {
#pragma unroll
            for (int nf = 0; nf < 8; nf++) {
                int key = j0 + nf * 8 + 2 * tig;
                if (key     > qi0) sacc[nf][0] = -CUDART_INF_F;
                if (key + 1 > qi0) sacc[nf][1] = -CUDART_INF_F;
                if (key     > qi1) sacc[nf][2] = -CUDART_INF_F;
                if (key + 1 > qi1) sacc[nf][3] = -CUDART_INF_F;
            }
        }

        // ---- online softmax (scale folded into exponent) ----
        float mx0 = -CUDART_INF_F, mx1 = -CUDART_INF_F;
#pragma unroll
        for (int nf = 0; nf < 8; nf++) {
            mx0 = fmaxf(mx0, fmaxf(sacc[nf][0], sacc[nf][1]));
            mx1 = fmaxf(mx1, fmaxf(sacc[nf][2], sacc[nf][3]));
        }
        mx0 = fmaxf(mx0, __shfl_xor_sync(0xffffffffu, mx0, 1));
        mx0 = fmaxf(mx0, __shfl_xor_sync(0xffffffffu, mx0, 2));
        mx1 = fmaxf(mx1, __shfl_xor_sync(0xffffffffu, mx1, 1));
        mx1 = fmaxf(mx1, __shfl_xor_sync(0xffffffffu, mx1, 2));

        float m0n = fmaxf(m0, mx0);
        float m1n = fmaxf(m1, mx1);
        float alpha0 = __expf((m0 - m0n) * ATT_SCALE);
        float alpha1 = __expf((m1 - m1n) * ATT_SCALE);
        m0 = m0n; m1 = m1n;

        float rs0 = 0.f, rs1 = 0.f;
#pragma unroll
        for (int nf = 0; nf < 8; nf++) {
            float p0 = __expf((sacc[nf][0] - m0) * ATT_SCALE);
            float p1 = __expf((sacc[nf][1] - m0) * ATT_SCALE);
            float p2 = __expf((sacc[nf][2] - m1) * ATT_SCALE);
            float p3 = __expf((sacc[nf][3] - m1) * ATT_SCALE);
            rs0 += p0 + p1;
            rs1 += p2 + p3;
            *(float2*)&Pw[grp * AT_PS + nf * 8 + 2 * tig] =
                make_float2(f2tf32f(p0), f2tf32f(p1));
            *(float2*)&Pw[(grp + 8) * AT_PS + nf * 8 + 2 * tig] =
                make_float2(f2tf32f(p2), f2tf32f(p3));
        }
        rs0 += __shfl_xor_sync(0xffffffffu, rs0, 1);
        rs0 += __shfl_xor_sync(0xffffffffu, rs0, 2);
        rs1 += __shfl_xor_sync(0xffffffffu, rs1, 1);
        rs1 += __shfl_xor_sync(0xffffffffu, rs1, 2);
        l0 = l0 * alpha0 + rs0;
        l1 = l1 * alpha1 + rs1;

#pragma unroll
        for (int nf = 0; nf < 16; nf++) {
            of[nf][0] *= alpha0; of[nf][1] *= alpha0;
            of[nf][2] *= alpha1; of[nf][3] *= alpha1;
        }
        __syncwarp();

        // ---- O += P V ----
#pragma unroll
        for (int ks = 0; ks < 8; ks++) {
            unsigned af[4];
            af[0] = __float_as_uint(Pw[grp * AT_PS + ks * 8 + tig]);
            af[1] = __float_as_uint(Pw[(grp + 8) * AT_PS + ks * 8 + tig]);
            af[2] = __float_as_uint(Pw[grp * AT_PS + ks * 8 + tig + 4]);
            af[3] = __float_as_uint(Pw[(grp + 8) * AT_PS + ks * 8 + tig + 4]);
            const float* vrow0 = Vs + (ks * 8 + tig) * AT_STRIDE;
            const float* vrow1 = Vs + (ks * 8 + tig + 4) * AT_STRIDE;
#pragma unroll
            for (int nf = 0; nf < 16; nf++) {
                unsigned bf[2];
                bf[0] = __float_as_uint(vrow0[nf * 8 + grp]);
                bf[1] = __float_as_uint(vrow1[nf * 8 + grp]);
                mma_tf32(of[nf], af, bf);
            }
        }
        __syncthreads();   // all warps done with this buf before it is refilled
    }

    // ---- epilogue: normalize, tf32-round (GEMM2 operand), write ----
    float inv0 = 1.0f / l0, inv1 = 1.0f / l1;
    int r0 = i0 + warp * 16 + grp;
    float* dst0 = y + (size_t)(b * SEQ + r0) * DIMV + h * HD;
    float* dst1 = y + (size_t)(b * SEQ + r0 + 8) * DIMV + h * HD;
#pragma unroll
    for (int nf = 0; nf < 16; nf++) {
        *(float2*)(dst0 + nf * 8 + 2 * tig) =
            make_float2(f2tf32f(of[nf][0] * inv0), f2tf32f(of[nf][1] * inv0));
        *(float2*)(dst1 + nf * 8 + 2 * tig) =
            make_float2(f2tf32f(of[nf][2] * inv1), f2tf32f(of[nf][3] * inv1));
    }
}

// ================= launch =================
extern "C" void kernel_launch(void* const* d_in, const int* in_sizes, int n_in,
                              void* d_out, int out_size)
{
    const float* x    = (const float*)d_in[0];
    const float* Wqkv = (const float*)d_in[1];
    const float* Wout = (const float*)d_in[2];
    float* out = (float*)d_out;

    float *qkv, *y, *xr, *wqr, *wor, *ct, *st;
    cudaGetSymbolAddress((void**)&qkv, g_qkv);
    cudaGetSymbolAddress((void**)&y,   g_y);
    cudaGetSymbolAddress((void**)&xr,  g_xr);
    cudaGetSymbolAddress((void**)&wqr, g_wqr);
    cudaGetSymbolAddress((void**)&wor, g_wor);
    cudaGetSymbolAddress((void**)&ct,  g_cos);
    cudaGetSymbolAddress((void**)&st,  g_sin);

    // 1. RoPE tables + operand pre-rounding (one-time passes)
    rope_table_kernel<<<(SEQ * HALF + 255) / 256, 256>>>(ct, st);
    round_copy_kernel<<<(int)(((size_t)NTOK * DIMV / 4 + 255) / 256), 256>>>(
        x, xr, (size_t)NTOK * DIMV / 4);
    round_copy_kernel<<<(int)(((size_t)DIMV * QKVW / 4 + 255) / 256), 256>>>(
        Wqkv, wqr, (size_t)DIMV * QKVW / 4);
    round_copy_kernel<<<(int)(((size_t)DIMV * DIMV / 4 + 255) / 256), 256>>>(
        Wout, wor, (size_t)DIMV * DIMV / 4);

    // 2. QKV projection (TF32 mma.sync, pre-rounded operands)
    cudaFuncSetAttribute(gemm_tf32_kernel, cudaFuncAttributeMaxDynamicSharedMemorySize, GEMM_SMEM_BYTES);
    gemm_tf32_kernel<<<dim3(QKVW / BN, NTOK / BM), 256, GEMM_SMEM_BYTES>>>(
        xr, wqr, qkv, NTOK, QKVW, DIMV);

    // 3. RMS-norm + RoPE (+ tf32 rounding of q,k,v)
    rmsrope_kernel<<<dim3(NTOK, NHEAD + 2 * NKV), 128>>>(qkv, ct, st);

    // 4. causal GQA flash attention (TF32 mma.sync, cp.async double buffer)
    cudaFuncSetAttribute(attn_mma_kernel, cudaFuncAttributeMaxDynamicSharedMemorySize, AT_SMEM_BYTES);
    attn_mma_kernel<<<dim3(SEQ / 128, BATCH * NHEAD), 256, AT_SMEM_BYTES>>>(qkv, y);

    // 5. output projection (TF32 mma.sync, pre-rounded operands)
    gemm_tf32_kernel<<<dim3(DIMV / BN, NTOK / BM), 256, GEMM_SMEM_BYTES>>>(
        y, wor, out, NTOK, DIMV, DIMV);
}

// round 6
// speedup vs baseline: 6.7072x; 2.3246x over previous
#include <cuda_runtime.h>
#include <cuda_fp16.h>
#include <math.h>
#include <math_constants.h>
#include <cstdint>

// ---------------- problem constants ----------------
#define DIMV   2048
#define SEQ    2048
#define BATCH  4
#define NHEAD  16
#define NKV    4
#define HD     128
#define HALF   64
#define QKVW   (DIMV + 2 * NKV * HD)   // 3072
#define NTOK   (BATCH * SEQ)           // 8192
#define RMS_EPS 1.1920929e-07f
#define ATT_SCALE 0.08838834764831845f // 1/sqrt(128)

// ---------------- scratch ----------------
__device__ float  g_qkv[(size_t)NTOK * QKVW];    // 96 MB fp32 (GEMM1 out)
__device__ __half g_qkvh[(size_t)NTOK * QKVW];   // 48 MB (normed/roped, half)
__device__ __half g_yh[(size_t)NTOK * DIMV];     // 32 MB (attention out, half)
__device__ __half g_xh[(size_t)NTOK * DIMV];     // 32 MB (x as half)
__device__ __half g_wqh[(size_t)QKVW * DIMV];    // 12 MB (W_qkv^T half, [N][K])
__device__ __half g_woh[(size_t)DIMV * DIMV];    //  8 MB (W_out^T half, [N][K])
__device__ float  g_cos[SEQ * HALF];
__device__ float  g_sin[SEQ * HALF];

// ---------------- helpers ----------------
__device__ __forceinline__ void cp_async16(void* dst_smem, const void* src_gmem) {
    unsigned d = (unsigned)__cvta_generic_to_shared(dst_smem);
    asm volatile("cp.async.cg.shared.global [%0], [%1], 16;\n" :: "r"(d), "l"(src_gmem));
}
#define CP_COMMIT asm volatile("cp.async.commit_group;\n" ::: "memory")
#define CP_WAIT0  asm volatile("cp.async.wait_group 0;\n" ::: "memory")
#define CP_WAIT1  asm volatile("cp.async.wait_group 1;\n" ::: "memory")

__device__ __forceinline__ uint32_t smem_u32(const void* p) {
    uint32_t a;
    asm("{ .reg .u64 t; cvta.to.shared.u64 t, %1; cvt.u32.u64 %0, t; }" : "=r"(a) : "l"(p));
    return a;
}

__device__ __forceinline__ void ldsm_x4(uint32_t addr, unsigned* r) {
    asm volatile("ldmatrix.sync.aligned.m8n8.x4.shared.b16 {%0,%1,%2,%3}, [%4];"
                 : "=r"(r[0]), "=r"(r[1]), "=r"(r[2]), "=r"(r[3]) : "r"(addr));
}
__device__ __forceinline__ void ldsm_x4_t(uint32_t addr, unsigned* r) {
    asm volatile("ldmatrix.sync.aligned.m8n8.x4.trans.shared.b16 {%0,%1,%2,%3}, [%4];"
                 : "=r"(r[0]), "=r"(r[1]), "=r"(r[2]), "=r"(r[3]) : "r"(addr));
}
__device__ __forceinline__ void mma_f16(float* c, const unsigned* a, const unsigned* b) {
    asm volatile(
        "mma.sync.aligned.m16n8k16.row.col.f32.f16.f16.f32 "
        "{%0,%1,%2,%3}, {%4,%5,%6,%7}, {%8,%9}, {%0,%1,%2,%3};\n"
        : "+f"(c[0]), "+f"(c[1]), "+f"(c[2]), "+f"(c[3])
        : "r"(a[0]), "r"(a[1]), "r"(a[2]), "r"(a[3]), "r"(b[0]), "r"(b[1]));
}
__device__ __forceinline__ unsigned packh2(float lo, float hi) {
    __half2 h = __halves2half2(__float2half_rn(lo), __float2half_rn(hi));
    return *(unsigned*)&h;
}

// ================= RoPE table (double-precision angles) =================
__global__ void rope_table_kernel(float* __restrict__ ct, float* __restrict__ st) {
    int idx = blockIdx.x * blockDim.x + threadIdx.x;
    if (idx >= SEQ * HALF) return;
    int s = idx >> 6;
    int f = idx & 63;
    double inv = pow(10000.0, -((double)(2 * f)) / 128.0);
    double th = (double)s * inv;
    ct[idx] = (float)cos(th);
    st[idx] = (float)sin(th);
}

// ================= fp32 -> fp16 copy =================
__global__ __launch_bounds__(256) void half_copy_kernel(
    const float* __restrict__ src, __half* __restrict__ dst, size_t n4)
{
    size_t i = (size_t)blockIdx.x * blockDim.x + threadIdx.x;
    if (i >= n4) return;
    float4 v = ((const float4*)src)[i];
    __half2 a = __halves2half2(__float2half_rn(v.x), __float2half_rn(v.y));
    __half2 b = __halves2half2(__float2half_rn(v.z), __float2half_rn(v.w));
    ((__half2*)dst)[2 * i]     = a;
    ((__half2*)dst)[2 * i + 1] = b;
}

// ================= transpose + fp16: dst[C][R] = half(src[R][C]) =================
__global__ __launch_bounds__(256) void transpose_half_kernel(
    const float* __restrict__ src, __half* __restrict__ dst, int R, int C)
{
    __shared__ float t[32][33];
    int c0 = blockIdx.x * 32, r0 = blockIdx.y * 32;
#pragma unroll
    for (int j = 0; j < 4; j++) {
        int row = r0 + threadIdx.y + j * 8;
        t[threadIdx.y + j * 8][threadIdx.x] = src[(size_t)row * C + c0 + threadIdx.x];
    }
    __syncthreads();
#pragma unroll
    for (int j = 0; j < 4; j++) {
        int col = c0 + threadIdx.y + j * 8;
        dst[(size_t)col * R + r0 + threadIdx.x] = __float2half_rn(t[threadIdx.x][threadIdx.y + j * 8]);
    }
}

// ======================================================================
// FP16 tensor-core GEMM: C[M,N] = A[M,K] @ Bt[N,K]^T  (A, Bt half, K-major)
// CTA 128x256, BK=64, 3-stage cp.async, 8 warps (2x4), warp tile 64x64,
// mma.m16n8k16, ldmatrix fragments, SW128-style swizzle (16B unit XOR row&7).
// ======================================================================
#define GBM 128
#define GBN 256
#define GBK 64
#define GA_BYTES (GBM * GBK * 2)          // 16384
#define GB_BYTES (GBN * GBK * 2)          // 32768
#define GSTAGE_BYTES (GA_BYTES + GB_BYTES) // 49152
#define GSMEM_BYTES (3 * GSTAGE_BYTES)     // 147456

__global__ __launch_bounds__(256, 1) void gemm_f16_kernel(
    const __half* __restrict__ A, const __half* __restrict__ Bt, float* __restrict__ C,
    int M, int N, int K)
{
    extern __shared__ char smc[];
    const uint32_t sbase = smem_u32(smc);
    const int tid = threadIdx.x;
    const int warp = tid >> 5;
    const int lane = tid & 31;
    const int grp = lane >> 2;
    const int tig = lane & 3;
    const int wm = warp >> 2;
    const int wn = warp & 3;
    const int row0 = blockIdx.y * GBM;
    const int col0 = blockIdx.x * GBN;
    const int NIT = K / GBK;

    auto issue_load = [&](int buf, int k0) {
        char* s = smc + buf * GSTAGE_BYTES;
#pragma unroll
        for (int rep = 0; rep < 4; rep++) {           // A: 1024 16B chunks
            int idx = tid + rep * 256;
            int m = idx >> 3, c16 = idx & 7;
            cp_async16(s + m * 128 + ((c16 ^ (m & 7)) << 4),
                       A + (size_t)(row0 + m) * K + k0 + c16 * 8);
        }
        char* sb = s + GA_BYTES;
#pragma unroll
        for (int rep = 0; rep < 8; rep++) {           // B: 2048 16B chunks
            int idx = tid + rep * 256;
            int n = idx >> 3, c16 = idx & 7;
            cp_async16(sb + n * 128 + ((c16 ^ (n & 7)) << 4),
                       Bt + (size_t)(col0 + n) * K + k0 + c16 * 8);
        }
    };

    float acc[4][8][4];
#pragma unroll
    for (int mt = 0; mt < 4; mt++)
#pragma unroll
        for (int nt = 0; nt < 8; nt++)
#pragma unroll
            for (int r = 0; r < 4; r++) acc[mt][nt][r] = 0.f;

    // fragment lane geometry
    const int arow_off = ((lane >> 3) & 1) * 8 + (lane & 7);  // A/Q pattern
    const int aseg_hi  = lane >> 4;                           // 0/1 -> k+8
    const int brow_off = ((lane >> 4) & 1) * 8 + (lane & 7);  // B pattern
    const int bseg_hi  = (lane >> 3) & 1;

    issue_load(0, 0); CP_COMMIT;
    issue_load(1, GBK); CP_COMMIT;

    int buf = 0, nbuf = 2;
    for (int it = 0; it < NIT; it++) {
        CP_WAIT1;
        __syncthreads();
        if (it + 2 < NIT) issue_load(nbuf, (it + 2) * GBK);
        CP_COMMIT;

        const uint32_t sA = sbase + buf * GSTAGE_BYTES;
        const uint32_t sB = sA + GA_BYTES;

#pragma unroll
        for (int ks = 0; ks < 4; ks++) {
            unsigned af[4][4], bf[4][4];
#pragma unroll
            for (int mt = 0; mt < 4; mt++) {
                int row = wm * 64 + mt * 16 + arow_off;
                int seg = ks * 2 + aseg_hi;
                ldsm_x4(sA + row * 128 + ((seg ^ (row & 7)) << 4), af[mt]);
            }
#pragma unroll
            for (int p = 0; p < 4; p++) {
                int row = wn * 64 + p * 16 + brow_off;
                int seg = ks * 2 + bseg_hi;
                ldsm_x4(sB + row * 128 + ((seg ^ (row & 7)) << 4), bf[p]);
            }
#pragma unroll
            for (int mt = 0; mt < 4; mt++)
#pragma unroll
                for (int nt = 0; nt < 8; nt++)
                    mma_f16(acc[mt][nt], af[mt], (nt & 1) ? &bf[nt >> 1][2] : &bf[nt >> 1][0]);
        }
        __syncthreads();
        buf = (buf == 2) ? 0 : buf + 1;
        nbuf = (nbuf == 2) ? 0 : nbuf + 1;
    }

#pragma unroll
    for (int mt = 0; mt < 4; mt++) {
        int row = row0 + wm * 64 + mt * 16 + grp;
#pragma unroll
        for (int nt = 0; nt < 8; nt++) {
            int col = col0 + wn * 64 + nt * 8 + tig * 2;
            float* c0 = C + (size_t)row * N + col;
            float* c1 = C + (size_t)(row + 8) * N + col;
            *(float2*)c0 = make_float2(acc[mt][nt][0], acc[mt][nt][1]);
            *(float2*)c1 = make_float2(acc[mt][nt][2], acc[mt][nt][3]);
        }
    }
}

// ================= RMS-norm + RoPE, fp32 in -> fp16 out =================
// grid (NTOK, 24): 0..15 q (norm+rope), 16..19 k (norm+rope), 20..23 v (convert)
__global__ __launch_bounds__(128) void rmsrope_kernel(
    const float* __restrict__ qkv, __half* __restrict__ qkvh,
    const float* __restrict__ ct, const float* __restrict__ st)
{
    const int row = blockIdx.x;
    const int hh = blockIdx.y;
    const int s = row & (SEQ - 1);
    const int t = threadIdx.x;

    if (hh >= NHEAD + NKV) {
        const int col = DIMV + NKV * HD + (hh - NHEAD - NKV) * HD;
        qkvh[(size_t)row * QKVW + col + t] =
            __float2half_rn(qkv[(size_t)row * QKVW + col + t]);
        return;
    }

    const int col = (hh < NHEAD) ? hh * HD : DIMV + (hh - NHEAD) * HD;
    const float* p = qkv + (size_t)row * QKVW + col;

    float v = p[t];
    float sq = v * v;
#pragma unroll
    for (int off = 16; off; off >>= 1) sq += __shfl_xor_sync(0xffffffffu, sq, off);

    __shared__ float red[4];
    __shared__ float xs[128];
    if ((t & 31) == 0) red[t >> 5] = sq;
    __syncthreads();
    float total = red[0] + red[1] + red[2] + red[3];
    float sc = rsqrtf(total * (1.0f / 128.0f) + RMS_EPS);
    float xn = v * sc;
    xs[t] = xn;
    __syncthreads();

    float out;
    if (t < HALF) {
        float c = ct[s * HALF + t], sn = st[s * HALF + t];
        out = xn * c + xs[t + HALF] * sn;
    } else {
        int f = t - HALF;
        float c = ct[s * HALF + f], sn = st[s * HALF + f];
        out = xn * c - xs[f] * sn;
    }
    qkvh[(size_t)row * QKVW + col + t] = __float2half_rn(out);
}

// ======================================================================
// FP16 flash attention: BM=128 Q rows/CTA, BN=64 keys/iter, D=128, GQA causal.
// mma.m16n8k16; Q frags register-resident; P register-resident (C->A frag remap);
// K via ldmatrix, V via ldmatrix.trans; cp.async double-buffered K/V tiles.
// smem: 2 stages x (K 16KB + V 16KB) = 64KB; Q staging aliases the region.
// ======================================================================
#define AT_SMEM_BYTES 65536

__global__ __launch_bounds__(256, 1) void attn_f16_kernel(
    const __half* __restrict__ qkvh, __half* __restrict__ yh)
{
    extern __shared__ char smc[];
    const uint32_t sbase = smem_u32(smc);
    const int tid = threadIdx.x;
    const int warp = tid >> 5;
    const int lane = tid & 31;
    const int grp = lane >> 2;
    const int tig = lane & 3;

    const int i0 = (gridDim.x - 1 - blockIdx.x) * 128;   // heavy tiles first
    const int bh = blockIdx.y;
    const int b = bh >> 4;
    const int h = bh & 15;
    const int kvh = h >> 2;

    const size_t rowb = (size_t)b * SEQ * QKVW;
    const int qcol = h * HD;
    const int kcol = DIMV + kvh * HD;
    const int vcol = DIMV + NKV * HD + kvh * HD;

    // ---- stage Q (half) into sm[0..32KB), swizzled ----
#pragma unroll
    for (int rep = 0; rep < 8; rep++) {
        int idx = tid + rep * 256;
        int row = idx >> 4, seg = idx & 15;
        cp_async16(smc + row * 256 + ((seg ^ (row & 7)) << 4),
                   qkvh + rowb + (size_t)(i0 + row) * QKVW + qcol + seg * 8);
    }
    CP_COMMIT; CP_WAIT0;
    __syncthreads();

    // ---- extract Q fragments (8 k-steps) ----
    const int arow_off = ((lane >> 3) & 1) * 8 + (lane & 7);
    const int aseg_hi  = lane >> 4;
    unsigned qf[8][4];
    {
        int row = warp * 16 + arow_off;
#pragma unroll
        for (int ks = 0; ks < 8; ks++) {
            int seg = ks * 2 + aseg_hi;
            ldsm_x4(sbase + row * 256 + ((seg ^ (row & 7)) << 4), qf[ks]);
        }
    }
    __syncthreads();   // Q reads done; KV buffers may overwrite

    auto issue_kv = [&](int buf, int j0) {
        char* Ks = smc + buf * 32768;
        char* Vs = Ks + 16384;
#pragma unroll
        for (int rep = 0; rep < 4; rep++) {
            int idx = tid + rep * 256;          // 0..1023
            int row = idx >> 4, seg = idx & 15;
            const __half* kr = qkvh + rowb + (size_t)(j0 + row) * QKVW;
            uint32_t d = row * 256 + ((seg ^ (row & 7)) << 4);
            cp_async16(Ks + d, kr + kcol + seg * 8);
            cp_async16(Vs + d, kr + vcol + seg * 8);
        }
    };

    float of[16][4];
#pragma unroll
    for (int nf = 0; nf < 16; nf++)
#pragma unroll
        for (int r = 0; r < 4; r++) of[nf][r] = 0.f;
    float m0 = -CUDART_INF_F, m1 = -CUDART_INF_F, l0 = 0.f, l1 = 0.f;

    const int qi0 = i0 + warp * 16 + grp;
    const int qi1 = qi0 + 8;
    const int NIT = (i0 + 128) / 64;

    const int brow_off = ((lane >> 4) & 1) * 8 + (lane & 7);   // K frag pattern
    const int bseg_hi  = (lane >> 3) & 1;
    const int vrow_off = ((lane >> 3) & 1) * 8 + (lane & 7);   // V trans pattern
    const int vseg_hi  = (lane >> 4) & 1;

    issue_kv(0, 0); CP_COMMIT;

    for (int it = 0; it < NIT; it++) {
        const int j0 = it * 64;
        const int buf = it & 1;
        if (it + 1 < NIT) issue_kv(buf ^ 1, j0 + 64);
        CP_COMMIT;
        CP_WAIT1;
        __syncthreads();

        const uint32_t Kb = sbase + buf * 32768;
        const uint32_t Vb = Kb + 16384;

        // ---- S = Q K^T ----
        float sacc[8][4];
#pragma unroll
        for (int nf = 0; nf < 8; nf++)
#pragma unroll
            for (int r = 0; r < 4; r++) sacc[nf][r] = 0.f;

#pragma unroll
        for (int ks = 0; ks < 8; ks++) {
            unsigned bf[4][4];
#pragma unroll
            for (int p = 0; p < 4; p++) {
                int row = p * 16 + brow_off;
                int seg = ks * 2 + bseg_hi;
                ldsm_x4(Kb + row * 256 + ((seg ^ (row & 7)) << 4), bf[p]);
            }
#pragma unroll
            for (int nf = 0; nf < 8; nf++)
                mma_f16(sacc[nf], qf[ks], (nf & 1) ? &bf[nf >> 1][2] : &bf[nf >> 1][0]);
        }

        // ---- causal mask ----
        if (j0 + 63 > i0) {
#pragma unroll
            for (int nf = 0; nf < 8; nf++) {
                int key = j0 + nf * 8 + 2 * tig;
                if (key     > qi0) sacc[nf][0] = -CUDART_INF_F;
                if (key + 1 > qi0) sacc[nf][1] = -CUDART_INF_F;
                if (key     > qi1) sacc[nf][2] = -CUDART_INF_F;
                if (key + 1 > qi1) sacc[nf][3] = -CUDART_INF_F;
            }
        }

        // ---- online softmax (scale folded into exponent) ----
        float mx0 = -CUDART_INF_F, mx1 = -CUDART_INF_F;
#pragma unroll
        for (int nf = 0; nf < 8; nf++) {
            mx0 = fmaxf(mx0, fmaxf(sacc[nf][0], sacc[nf][1]));
            mx1 = fmaxf(mx1, fmaxf(sacc[nf][2], sacc[nf][3]));
        }
        mx0 = fmaxf(mx0, __shfl_xor_sync(0xffffffffu, mx0, 1));
        mx0 = fmaxf(mx0, __shfl_xor_sync(0xffffffffu, mx0, 2));
        mx1 = fmaxf(mx1, __shfl_xor_sync(0xffffffffu, mx1, 1));
        mx1 = fmaxf(mx1, __shfl_xor_sync(0xffffffffu, mx1, 2));

        float m0n = fmaxf(m0, mx0);
        float m1n = fmaxf(m1, mx1);
        float alpha0 = __expf((m0 - m0n) * ATT_SCALE);
        float alpha1 = __expf((m1 - m1n) * ATT_SCALE);
        m0 = m0n; m1 = m1n;

        unsigned ph[8][2];
        float rs0 = 0.f, rs1 = 0.f;
#pragma unroll
        for (int nf = 0; nf < 8; nf++) {
            float p0 = __expf((sacc[nf][0] - m0) * ATT_SCALE);
            float p1 = __expf((sacc[nf][1] - m0) * ATT_SCALE);
            float p2 = __expf((sacc[nf][2] - m1) * ATT_SCALE);
            float p3 = __expf((sacc[nf][3] - m1) * ATT_SCALE);
            rs0 += p0 + p1;
            rs1 += p2 + p3;
            ph[nf][0] = packh2(p0, p1);
            ph[nf][1] = packh2(p2, p3);
        }
        rs0 += __shfl_xor_sync(0xffffffffu, rs0, 1);
        rs0 += __shfl_xor_sync(0xffffffffu, rs0, 2);
        rs1 += __shfl_xor_sync(0xffffffffu, rs1, 1);
        rs1 += __shfl_xor_sync(0xffffffffu, rs1, 2);
        l0 = l0 * alpha0 + rs0;
        l1 = l1 * alpha1 + rs1;

#pragma unroll
        for (int nf = 0; nf < 16; nf++) {
            of[nf][0] *= alpha0; of[nf][1] *= alpha0;
            of[nf][2] *= alpha1; of[nf][3] *= alpha1;
        }

        // ---- O += P V  (P in registers: C-frag -> A-frag remap) ----
#pragma unroll
        for (int ks = 0; ks < 4; ks++) {
            unsigned af[4] = {ph[2 * ks][0], ph[2 * ks][1],
                              ph[2 * ks + 1][0], ph[2 * ks + 1][1]};
#pragma unroll
            for (int p = 0; p < 8; p++) {
                int row = ks * 16 + vrow_off;
                int seg = p * 2 + vseg_hi;
                unsigned vf[4];
                ldsm_x4_t(Vb + row * 256 + ((seg ^ (row & 7)) << 4), vf);
                mma_f16(of[2 * p],     af, &vf[0]);
                mma_f16(of[2 * p + 1], af, &vf[2]);
            }
        }
        __syncthreads();   // all warps done with buf before refill
    }

    // ---- epilogue: normalize, fp16, write ----
    float inv0 = 1.0f / l0, inv1 = 1.0f / l1;
    int r0 = i0 + warp * 16 + grp;
    __half* dst0 = yh + (size_t)(b * SEQ + r0) * DIMV + h * HD;
    __half* dst1 = yh + (size_t)(b * SEQ + r0 + 8) * DIMV + h * HD;
#pragma unroll
    for (int nf = 0; nf < 16; nf++) {
        unsigned u0 = packh2(of[nf][0] * inv0, of[nf][1] * inv0);
        unsigned u1 = packh2(of[nf][2] * inv1, of[nf][3] * inv1);
        *(unsigned*)(dst0 + nf * 8 + 2 * tig) = u0;
        *(unsigned*)(dst1 + nf * 8 + 2 * tig) = u1;
    }
}

// ================= launch =================
extern "C" void kernel_launch(void* const* d_in, const int* in_sizes, int n_in,
                              void* d_out, int out_size)
{
    const float* x    = (const float*)d_in[0];
    const float* Wqkv = (const float*)d_in[1];
    const float* Wout = (const float*)d_in[2];
    float* out = (float*)d_out;

    float *qkv, *ct, *st;
    __half *qkvh, *yh, *xh, *wqh, *woh;
    cudaGetSymbolAddress((void**)&qkv,  g_qkv);
    cudaGetSymbolAddress((void**)&qkvh, g_qkvh);
    cudaGetSymbolAddress((void**)&yh,   g_yh);
    cudaGetSymbolAddress((void**)&xh,   g_xh);
    cudaGetSymbolAddress((void**)&wqh,  g_wqh);
    cudaGetSymbolAddress((void**)&woh,  g_woh);
    cudaGetSymbolAddress((void**)&ct,   g_cos);
    cudaGetSymbolAddress((void**)&st,   g_sin);

    // 1. tables + operand conversion (one-time, ~35 us)
    rope_table_kernel<<<(SEQ * HALF + 255) / 256, 256>>>(ct, st);
    half_copy_kernel<<<(int)(((size_t)NTOK * DIMV / 4 + 255) / 256), 256>>>(
        x, xh, (size_t)NTOK * DIMV / 4);
    transpose_half_kernel<<<dim3(QKVW / 32, DIMV / 32), dim3(32, 8)>>>(Wqkv, wqh, DIMV, QKVW);
    transpose_half_kernel<<<dim3(DIMV / 32, DIMV / 32), dim3(32, 8)>>>(Wout, woh, DIMV, DIMV);

    // 2. QKV projection (fp16 mma, fp32 accum)
    cudaFuncSetAttribute(gemm_f16_kernel, cudaFuncAttributeMaxDynamicSharedMemorySize, GSMEM_BYTES);
    gemm_f16_kernel<<<dim3(QKVW / GBN, NTOK / GBM), 256, GSMEM_BYTES>>>(
        xh, wqh, qkv, NTOK, QKVW, DIMV);

    // 3. RMS-norm + RoPE -> fp16 qkv
    rmsrope_kernel<<<dim3(NTOK, NHEAD + 2 * NKV), 128>>>(qkv, qkvh, ct, st);

    // 4. causal GQA flash attention (fp16 mma, fp32 softmax/accum)
    cudaFuncSetAttribute(attn_f16_kernel, cudaFuncAttributeMaxDynamicSharedMemorySize, AT_SMEM_BYTES);
    attn_f16_kernel<<<dim3(SEQ / 128, BATCH * NHEAD), 256, AT_SMEM_BYTES>>>(qkvh, yh);

    // 5. output projection (fp16 mma, fp32 accum)
    gemm_f16_kernel<<<dim3(DIMV / GBN, NTOK / GBM), 256, GSMEM_BYTES>>>(
        yh, woh, out, NTOK, DIMV, DIMV);
}

// round 7
// speedup vs baseline: 7.5395x; 1.1241x over previous
#include <cuda_runtime.h>
#include <cuda_fp16.h>
#include <math.h>
#include <math_constants.h>
#include <cstdint>

// ---------------- problem constants ----------------
#define DIMV   2048
#define SEQ    2048
#define BATCH  4
#define NHEAD  16
#define NKV    4
#define HD     128
#define HALF   64
#define QKVW   (DIMV + 2 * NKV * HD)   // 3072
#define NTOK   (BATCH * SEQ)           // 8192
#define RMS_EPS 1.1920929e-07f
#define ATT_SCALE 0.08838834764831845f // 1/sqrt(128)

// ---------------- scratch ----------------
__device__ __half g_qkvh[(size_t)NTOK * QKVW];   // 48 MB (normed/roped, half)
__device__ __half g_yh[(size_t)NTOK * DIMV];     // 32 MB (attention out, half)
__device__ __half g_xh[(size_t)NTOK * DIMV];     // 32 MB (x as half)
__device__ __half g_wqh[(size_t)QKVW * DIMV];    // 12 MB (W_qkv^T half, [N][K])
__device__ __half g_woh[(size_t)DIMV * DIMV];    //  8 MB (W_out^T half, [N][K])
__device__ float  g_cos[SEQ * HALF];
__device__ float  g_sin[SEQ * HALF];

// ---------------- helpers ----------------
__device__ __forceinline__ void cp_async16(void* dst_smem, const void* src_gmem) {
    unsigned d = (unsigned)__cvta_generic_to_shared(dst_smem);
    asm volatile("cp.async.cg.shared.global [%0], [%1], 16;\n" :: "r"(d), "l"(src_gmem));
}
#define CP_COMMIT asm volatile("cp.async.commit_group;\n" ::: "memory")
#define CP_WAIT0  asm volatile("cp.async.wait_group 0;\n" ::: "memory")
#define CP_WAIT1  asm volatile("cp.async.wait_group 1;\n" ::: "memory")

__device__ __forceinline__ uint32_t smem_u32(const void* p) {
    uint32_t a;
    asm("{ .reg .u64 t; cvta.to.shared.u64 t, %1; cvt.u32.u64 %0, t; }" : "=r"(a) : "l"(p));
    return a;
}
__device__ __forceinline__ void ldsm_x4(uint32_t addr, unsigned* r) {
    asm volatile("ldmatrix.sync.aligned.m8n8.x4.shared.b16 {%0,%1,%2,%3}, [%4];"
                 : "=r"(r[0]), "=r"(r[1]), "=r"(r[2]), "=r"(r[3]) : "r"(addr));
}
__device__ __forceinline__ void ldsm_x4_t(uint32_t addr, unsigned* r) {
    asm volatile("ldmatrix.sync.aligned.m8n8.x4.trans.shared.b16 {%0,%1,%2,%3}, [%4];"
                 : "=r"(r[0]), "=r"(r[1]), "=r"(r[2]), "=r"(r[3]) : "r"(addr));
}
__device__ __forceinline__ void mma_f16(float* c, const unsigned* a, const unsigned* b) {
    asm volatile(
        "mma.sync.aligned.m16n8k16.row.col.f32.f16.f16.f32 "
        "{%0,%1,%2,%3}, {%4,%5,%6,%7}, {%8,%9}, {%0,%1,%2,%3};\n"
        : "+f"(c[0]), "+f"(c[1]), "+f"(c[2]), "+f"(c[3])
        : "r"(a[0]), "r"(a[1]), "r"(a[2]), "r"(a[3]), "r"(b[0]), "r"(b[1]));
}
__device__ __forceinline__ unsigned packh2(float lo, float hi) {
    __half2 h = __halves2half2(__float2half_rn(lo), __float2half_rn(hi));
    return *(unsigned*)&h;
}

// ================= RoPE table (double-precision angles) =================
__global__ void rope_table_kernel(float* __restrict__ ct, float* __restrict__ st) {
    int idx = blockIdx.x * blockDim.x + threadIdx.x;
    if (idx >= SEQ * HALF) return;
    int s = idx >> 6;
    int f = idx & 63;
    double inv = pow(10000.0, -((double)(2 * f)) / 128.0);
    double th = (double)s * inv;
    ct[idx] = (float)cos(th);
    st[idx] = (float)sin(th);
}

// ================= fp32 -> fp16 copy =================
__global__ __launch_bounds__(256) void half_copy_kernel(
    const float* __restrict__ src, __half* __restrict__ dst, size_t n4)
{
    size_t i = (size_t)blockIdx.x * blockDim.x + threadIdx.x;
    if (i >= n4) return;
    float4 v = ((const float4*)src)[i];
    ((__half2*)dst)[2 * i]     = __halves2half2(__float2half_rn(v.x), __float2half_rn(v.y));
    ((__half2*)dst)[2 * i + 1] = __halves2half2(__float2half_rn(v.z), __float2half_rn(v.w));
}

// ================= transpose + fp16: dst[C][R] = half(src[R][C]) =================
__global__ __launch_bounds__(256) void transpose_half_kernel(
    const float* __restrict__ src, __half* __restrict__ dst, int R, int C)
{
    __shared__ float t[32][33];
    int c0 = blockIdx.x * 32, r0 = blockIdx.y * 32;
#pragma unroll
    for (int j = 0; j < 4; j++) {
        int row = r0 + threadIdx.y + j * 8;
        t[threadIdx.y + j * 8][threadIdx.x] = src[(size_t)row * C + c0 + threadIdx.x];
    }
    __syncthreads();
#pragma unroll
    for (int j = 0; j < 4; j++) {
        int col = c0 + threadIdx.y + j * 8;
        dst[(size_t)col * R + r0 + threadIdx.x] = __float2half_rn(t[threadIdx.x][threadIdx.y + j * 8]);
    }
}

// ---------------- shared GEMM geometry ----------------
#define GBM 128
#define GBN 256
#define GBK 64
#define GA_BYTES (GBM * GBK * 2)           // 16384
#define GB_BYTES (GBN * GBK * 2)           // 32768
#define GSTAGE_BYTES (GA_BYTES + GB_BYTES) // 49152
#define GSMEM_BYTES (3 * GSTAGE_BYTES)     // 147456

// mainloop shared by both GEMMs (macro to keep one code path)
#define GEMM_MAINLOOP(Aptr, Bptr, Kdim)                                            \
    auto issue_load = [&](int bufi, int k0) {                                      \
        char* s = smc + bufi * GSTAGE_BYTES;                                       \
        _Pragma("unroll")                                                          \
        for (int rep = 0; rep < 4; rep++) {                                        \
            int idx = tid + rep * 256;                                             \
            int m = idx >> 3, c16 = idx & 7;                                       \
            cp_async16(s + m * 128 + ((c16 ^ (m & 7)) << 4),                       \
                       (Aptr) + (size_t)(row0 + m) * (Kdim) + k0 + c16 * 8);       \
        }                                                                          \
        char* sb = s + GA_BYTES;                                                   \
        _Pragma("unroll")                                                          \
        for (int rep = 0; rep < 8; rep++) {                                        \
            int idx = tid + rep * 256;                                             \
            int n = idx >> 3, c16 = idx & 7;                                       \
            cp_async16(sb + n * 128 + ((c16 ^ (n & 7)) << 4),                      \
                       (Bptr) + (size_t)(col0 + n) * (Kdim) + k0 + c16 * 8);       \
        }                                                                          \
    };                                                                             \
    const int NIT = (Kdim) / GBK;                                                  \
    const int arow_off = ((lane >> 3) & 1) * 8 + (lane & 7);                       \
    const int aseg_hi  = lane >> 4;                                                \
    const int brow_off = ((lane >> 4) & 1) * 8 + (lane & 7);                       \
    const int bseg_hi  = (lane >> 3) & 1;                                          \
    issue_load(0, 0); CP_COMMIT;                                                   \
    issue_load(1, GBK); CP_COMMIT;                                                 \
    int buf = 0, nbuf = 2;                                                         \
    for (int it = 0; it < NIT; it++) {                                             \
        CP_WAIT1;                                                                  \
        __syncthreads();                                                           \
        if (it + 2 < NIT) issue_load(nbuf, (it + 2) * GBK);                        \
        CP_COMMIT;                                                                 \
        const uint32_t sA = sbase + buf * GSTAGE_BYTES;                            \
        const uint32_t sB = sA + GA_BYTES;                                         \
        _Pragma("unroll")                                                          \
        for (int ks = 0; ks < 4; ks++) {                                           \
            unsigned af[4][4], bfr[4][4];                                          \
            _Pragma("unroll")                                                      \
            for (int mt = 0; mt < 4; mt++) {                                       \
                int rrow = wm * 64 + mt * 16 + arow_off;                           \
                int seg = ks * 2 + aseg_hi;                                        \
                ldsm_x4(sA + rrow * 128 + ((seg ^ (rrow & 7)) << 4), af[mt]);      \
            }                                                                      \
            _Pragma("unroll")                                                      \
            for (int p = 0; p < 4; p++) {                                          \
                int rrow = wn * 64 + p * 16 + brow_off;                            \
                int seg = ks * 2 + bseg_hi;                                        \
                ldsm_x4(sB + rrow * 128 + ((seg ^ (rrow & 7)) << 4), bfr[p]);      \
            }                                                                      \
            _Pragma("unroll")                                                      \
            for (int mt = 0; mt < 4; mt++)                                         \
                _Pragma("unroll")                                                  \
                for (int nt = 0; nt < 8; nt++)                                     \
                    mma_f16(acc[mt][nt], af[mt],                                   \
                            (nt & 1) ? &bfr[nt >> 1][2] : &bfr[nt >> 1][0]);       \
        }                                                                          \
        __syncthreads();                                                           \
        buf = (buf == 2) ? 0 : buf + 1;                                            \
        nbuf = (nbuf == 2) ? 0 : nbuf + 1;                                         \
    }

// ======================================================================
// GEMM1 fused: qkvh = rmsnorm+rope( x @ Wqkv ) as fp16.
// CTA tile 128x256 = 2 full heads; blockIdx.x: 0..7 Q, 8..9 K, 10..11 V.
// Epilogue: CTA-local RMS reduce (shfl + smem), RoPE pair exchange via
// the (now free) pipeline smem, write half. V tiles: convert only.
// ======================================================================
#define XS_STRIDE 264
#define XS_BYTES (128 * XS_STRIDE * 4)    // 135168
#define PR_OFF   XS_BYTES                 // float[128][4] partial sums

__global__ __launch_bounds__(256, 1) void gemm1_fused_kernel(
    const __half* __restrict__ A, const __half* __restrict__ Bt,
    __half* __restrict__ qkvh,
    const float* __restrict__ ct, const float* __restrict__ st)
{
    extern __shared__ char smc[];
    const uint32_t sbase = smem_u32(smc);
    const int tid = threadIdx.x;
    const int warp = tid >> 5;
    const int lane = tid & 31;
    const int grp = lane >> 2;
    const int tig = lane & 3;
    const int wm = warp >> 2;
    const int wn = warp & 3;
    const int row0 = blockIdx.y * GBM;
    const int col0 = blockIdx.x * GBN;

    float acc[4][8][4];
#pragma unroll
    for (int mt = 0; mt < 4; mt++)
#pragma unroll
        for (int nt = 0; nt < 8; nt++)
#pragma unroll
            for (int r = 0; r < 4; r++) acc[mt][nt][r] = 0.f;

    GEMM_MAINLOOP(A, Bt, DIMV)

    if (blockIdx.x >= 10) {
        // ---- V heads: plain half convert ----
#pragma unroll
        for (int mt = 0; mt < 4; mt++) {
            int row = row0 + wm * 64 + mt * 16 + grp;
#pragma unroll
            for (int nt = 0; nt < 8; nt++) {
                int col = col0 + wn * 64 + nt * 8 + tig * 2;
                *(unsigned*)(qkvh + (size_t)row * QKVW + col) =
                    packh2(acc[mt][nt][0], acc[mt][nt][1]);
                *(unsigned*)(qkvh + (size_t)(row + 8) * QKVW + col) =
                    packh2(acc[mt][nt][2], acc[mt][nt][3]);
            }
        }
        return;
    }

    // ---- Q/K heads: fused RMS-norm + RoPE ----
    float* xs = (float*)smc;                 // [128][XS_STRIDE]
    float* pr = (float*)(smc + PR_OFF);      // [128][4]

    // 1. per-thread sum of squares per row (over this warp's 64-col band)
    float ss[4][2];
#pragma unroll
    for (int mt = 0; mt < 4; mt++) {
        float s0 = 0.f, s1 = 0.f;
#pragma unroll
        for (int nt = 0; nt < 8; nt++) {
            s0 += acc[mt][nt][0] * acc[mt][nt][0] + acc[mt][nt][1] * acc[mt][nt][1];
            s1 += acc[mt][nt][2] * acc[mt][nt][2] + acc[mt][nt][3] * acc[mt][nt][3];
        }
        s0 += __shfl_xor_sync(0xffffffffu, s0, 1);
        s0 += __shfl_xor_sync(0xffffffffu, s0, 2);
        s1 += __shfl_xor_sync(0xffffffffu, s1, 1);
        s1 += __shfl_xor_sync(0xffffffffu, s1, 2);
        ss[mt][0] = s0;
        ss[mt][1] = s1;
    }
    if (tig == 0) {
#pragma unroll
        for (int mt = 0; mt < 4; mt++) {
            pr[(wm * 64 + mt * 16 + grp) * 4 + wn]     = ss[mt][0];
            pr[(wm * 64 + mt * 16 + grp + 8) * 4 + wn] = ss[mt][1];
        }
    }
    __syncthreads();

    // 2. normalize into smem staging
    const int base = (wn >> 1) * 2;          // head half-pair selector
#pragma unroll
    for (int mt = 0; mt < 4; mt++) {
        int r0l = wm * 64 + mt * 16 + grp;
        int r1l = r0l + 8;
        float sc0 = rsqrtf((pr[r0l * 4 + base] + pr[r0l * 4 + base + 1]) * (1.0f / 128.0f) + RMS_EPS);
        float sc1 = rsqrtf((pr[r1l * 4 + base] + pr[r1l * 4 + base + 1]) * (1.0f / 128.0f) + RMS_EPS);
#pragma unroll
        for (int nt = 0; nt < 8; nt++) {
            int col = wn * 64 + nt * 8 + tig * 2;
            xs[r0l * XS_STRIDE + col]     = acc[mt][nt][0] * sc0;
            xs[r0l * XS_STRIDE + col + 1] = acc[mt][nt][1] * sc0;
            xs[r1l * XS_STRIDE + col]     = acc[mt][nt][2] * sc1;
            xs[r1l * XS_STRIDE + col + 1] = acc[mt][nt][3] * sc1;
        }
    }
    __syncthreads();

    // 3. RoPE (pair f with f+64 inside each head) + fp16 store
#pragma unroll 4
    for (int i = 0; i < 32; i++) {
        int slot = warp + 8 * i;             // 0..255 = 128 rows x 2 heads
        int row = slot >> 1;
        int head = slot & 1;
        int s = (row0 + row) & (SEQ - 1);
#pragma unroll
        for (int ff = 0; ff < 2; ff++) {
            int f = lane + ff * 32;          // 0..63
            float x1 = xs[row * XS_STRIDE + head * 128 + f];
            float x2 = xs[row * XS_STRIDE + head * 128 + f + 64];
            float c = ct[s * HALF + f], sn = st[s * HALF + f];
            size_t gb = (size_t)(row0 + row) * QKVW + col0 + head * 128 + f;
            qkvh[gb]      = __float2half_rn(x1 * c + x2 * sn);
            qkvh[gb + 64] = __float2half_rn(x2 * c - x1 * sn);
        }
    }
}

// ======================================================================
// GEMM2: C[M,N] fp32 = A[M,K] @ Bt[N,K]^T  (A, Bt half)
// ======================================================================
__global__ __launch_bounds__(256, 1) void gemm_f16_kernel(
    const __half* __restrict__ A, const __half* __restrict__ Bt, float* __restrict__ C,
    int M, int N, int K)
{
    extern __shared__ char smc[];
    const uint32_t sbase = smem_u32(smc);
    const int tid = threadIdx.x;
    const int warp = tid >> 5;
    const int lane = tid & 31;
    const int grp = lane >> 2;
    const int tig = lane & 3;
    const int wm = warp >> 2;
    const int wn = warp & 3;
    const int row0 = blockIdx.y * GBM;
    const int col0 = blockIdx.x * GBN;

    float acc[4][8][4];
#pragma unroll
    for (int mt = 0; mt < 4; mt++)
#pragma unroll
        for (int nt = 0; nt < 8; nt++)
#pragma unroll
            for (int r = 0; r < 4; r++) acc[mt][nt][r] = 0.f;

    GEMM_MAINLOOP(A, Bt, K)

#pragma unroll
    for (int mt = 0; mt < 4; mt++) {
        int row = row0 + wm * 64 + mt * 16 + grp;
#pragma unroll
        for (int nt = 0; nt < 8; nt++) {
            int col = col0 + wn * 64 + nt * 8 + tig * 2;
            float* c0 = C + (size_t)row * N + col;
            float* c1 = C + (size_t)(row + 8) * N + col;
            *(float2*)c0 = make_float2(acc[mt][nt][0], acc[mt][nt][1]);
            *(float2*)c1 = make_float2(acc[mt][nt][2], acc[mt][nt][3]);
        }
    }
}

// ======================================================================
// FP16 flash attention (unchanged from R6)
// ======================================================================
#define AT_SMEM_BYTES 65536

__global__ __launch_bounds__(256, 1) void attn_f16_kernel(
    const __half* __restrict__ qkvh, __half* __restrict__ yh)
{
    extern __shared__ char smc[];
    const uint32_t sbase = smem_u32(smc);
    const int tid = threadIdx.x;
    const int warp = tid >> 5;
    const int lane = tid & 31;
    const int grp = lane >> 2;
    const int tig = lane & 3;

    const int i0 = (gridDim.x - 1 - blockIdx.x) * 128;
    const int bh = blockIdx.y;
    const int b = bh >> 4;
    const int h = bh & 15;
    const int kvh = h >> 2;

    const size_t rowb = (size_t)b * SEQ * QKVW;
    const int qcol = h * HD;
    const int kcol = DIMV + kvh * HD;
    const int vcol = DIMV + NKV * HD + kvh * HD;

#pragma unroll
    for (int rep = 0; rep < 8; rep++) {
        int idx = tid + rep * 256;
        int row = idx >> 4, seg = idx & 15;
        cp_async16(smc + row * 256 + ((seg ^ (row & 7)) << 4),
                   qkvh + rowb + (size_t)(i0 + row) * QKVW + qcol + seg * 8);
    }
    CP_COMMIT; CP_WAIT0;
    __syncthreads();

    const int arow_off = ((lane >> 3) & 1) * 8 + (lane & 7);
    const int aseg_hi  = lane >> 4;
    unsigned qf[8][4];
    {
        int row = warp * 16 + arow_off;
#pragma unroll
        for (int ks = 0; ks < 8; ks++) {
            int seg = ks * 2 + aseg_hi;
            ldsm_x4(sbase + row * 256 + ((seg ^ (row & 7)) << 4), qf[ks]);
        }
    }
    __syncthreads();

    auto issue_kv = [&](int buf, int j0) {
        char* Ks = smc + buf * 32768;
        char* Vs = Ks + 16384;
#pragma unroll
        for (int rep = 0; rep < 4; rep++) {
            int idx = tid + rep * 256;
            int row = idx >> 4, seg = idx & 15;
            const __half* kr = qkvh + rowb + (size_t)(j0 + row) * QKVW;
            uint32_t d = row * 256 + ((seg ^ (row & 7)) << 4);
            cp_async16(Ks + d, kr + kcol + seg * 8);
            cp_async16(Vs + d, kr + vcol + seg * 8);
        }
    };

    float of[16][4];
#pragma unroll
    for (int nf = 0; nf < 16; nf++)
#pragma unroll
        for (int r = 0; r < 4; r++) of[nf][r] = 0.f;
    float m0 = -CUDART_INF_F, m1 = -CUDART_INF_F, l0 = 0.f, l1 = 0.f;

    const int qi0 = i0 + warp * 16 + grp;
    const int qi1 = qi0 + 8;
    const int NIT = (i0 + 128) / 64;

    const int brow_off = ((lane >> 4) & 1) * 8 + (lane & 7);
    const int bseg_hi  = (lane >> 3) & 1;
    const int vrow_off = ((lane >> 3) & 1) * 8 + (lane & 7);
    const int vseg_hi  = (lane >> 4) & 1;

    issue_kv(0, 0); CP_COMMIT;

    for (int it = 0; it < NIT; it++) {
        const int j0 = it * 64;
        const int buf = it & 1;
        if (it + 1 < NIT) issue_kv(buf ^ 1, j0 + 64);
        CP_COMMIT;
        CP_WAIT1;
        __syncthreads();

        const uint32_t Kb = sbase + buf * 32768;
        const uint32_t Vb = Kb + 16384;

        float sacc[8][4];
#pragma unroll
        for (int nf = 0; nf < 8; nf++)
#pragma unroll
            for (int r = 0; r < 4; r++) sacc[nf][r] = 0.f;

#pragma unroll
        for (int ks = 0; ks < 8; ks++) {
            unsigned bf[4][4];
#pragma unroll
            for (int p = 0; p < 4; p++) {
                int row = p * 16 + brow_off;
                int seg = ks * 2 + bseg_hi;
                ldsm_x4(Kb + row * 256 + ((seg ^ (row & 7)) << 4), bf[p]);
            }
#pragma unroll
            for (int nf = 0; nf < 8; nf++)
                mma_f16(sacc[nf], qf[ks], (nf & 1) ? &bf[nf >> 1][2] : &bf[nf >> 1][0]);
        }

        if (j0 + 63 > i0) {
#pragma unroll
            for (int nf = 0; nf < 8; nf++) {
                int key = j0 + nf * 8 + 2 * tig;
                if (key     > qi0) sacc[nf][0] = -CUDART_INF_F;
                if (key + 1 > qi0) sacc[nf][1] = -CUDART_INF_F;
                if (key     > qi1) sacc[nf][2] = -CUDART_INF_F;
                if (key + 1 > qi1) sacc[nf][3] = -CUDART_INF_F;
            }
        }

        float mx0 = -CUDART_INF_F, mx1 = -CUDART_INF_F;
#pragma unroll
        for (int nf = 0; nf < 8; nf++) {
            mx0 = fmaxf(mx0, fmaxf(sacc[nf][0], sacc[nf][1]));
            mx1 = fmaxf(mx1, fmaxf(sacc[nf][2], sacc[nf][3]));
        }
        mx0 = fmaxf(mx0, __shfl_xor_sync(0xffffffffu, mx0, 1));
        mx0 = fmaxf(mx0, __shfl_xor_sync(0xffffffffu, mx0, 2));
        mx1 = fmaxf(mx1, __shfl_xor_sync(0xffffffffu, mx1, 1));
        mx1 = fmaxf(mx1, __shfl_xor_sync(0xffffffffu, mx1, 2));

        float m0n = fmaxf(m0, mx0);
        float m1n = fmaxf(m1, mx1);
        float alpha0 = __expf((m0 - m0n) * ATT_SCALE);
        float alpha1 = __expf((m1 - m1n) * ATT_SCALE);
        m0 = m0n; m1 = m1n;

        unsigned ph[8][2];
        float rs0 = 0.f, rs1 = 0.f;
#pragma unroll
        for (int nf = 0; nf < 8; nf++) {
            float p0 = __expf((sacc[nf][0] - m0) * ATT_SCALE);
            float p1 = __expf((sacc[nf][1] - m0) * ATT_SCALE);
            float p2 = __expf((sacc[nf][2] - m1) * ATT_SCALE);
            float p3 = __expf((sacc[nf][3] - m1) * ATT_SCALE);
            rs0 += p0 + p1;
            rs1 += p2 + p3;
            ph[nf][0] = packh2(p0, p1);
            ph[nf][1] = packh2(p2, p3);
        }
        rs0 += __shfl_xor_sync(0xffffffffu, rs0, 1);
        rs0 += __shfl_xor_sync(0xffffffffu, rs0, 2);
        rs1 += __shfl_xor_sync(0xffffffffu, rs1, 1);
        rs1 += __shfl_xor_sync(0xffffffffu, rs1, 2);
        l0 = l0 * alpha0 + rs0;
        l1 = l1 * alpha1 + rs1;

#pragma unroll
        for (int nf = 0; nf < 16; nf++) {
            of[nf][0] *= alpha0; of[nf][1] *= alpha0;
            of[nf][2] *= alpha1; of[nf][3] *= alpha1;
        }

#pragma unroll
        for (int ks = 0; ks < 4; ks++) {
            unsigned af[4] = {ph[2 * ks][0], ph[2 * ks][1],
                              ph[2 * ks + 1][0], ph[2 * ks + 1][1]};
#pragma unroll
            for (int p = 0; p < 8; p++) {
                int row = ks * 16 + vrow_off;
                int seg = p * 2 + vseg_hi;
                unsigned vf[4];
                ldsm_x4_t(Vb + row * 256 + ((seg ^ (row & 7)) << 4), vf);
                mma_f16(of[2 * p],     af, &vf[0]);
                mma_f16(of[2 * p + 1], af, &vf[2]);
            }
        }
        __syncthreads();
    }

    float inv0 = 1.0f / l0, inv1 = 1.0f / l1;
    int r0 = i0 + warp * 16 + grp;
    __half* dst0 = yh + (size_t)(b * SEQ + r0) * DIMV + h * HD;
    __half* dst1 = yh + (size_t)(b * SEQ + r0 + 8) * DIMV + h * HD;
#pragma unroll
    for (int nf = 0; nf < 16; nf++) {
        *(unsigned*)(dst0 + nf * 8 + 2 * tig) = packh2(of[nf][0] * inv0, of[nf][1] * inv0);
        *(unsigned*)(dst1 + nf * 8 + 2 * tig) = packh2(of[nf][2] * inv1, of[nf][3] * inv1);
    }
}

// ================= launch =================
extern "C" void kernel_launch(void* const* d_in, const int* in_sizes, int n_in,
                              void* d_out, int out_size)
{
    const float* x    = (const float*)d_in[0];
    const float* Wqkv = (const float*)d_in[1];
    const float* Wout = (const float*)d_in[2];
    float* out = (float*)d_out;

    float *ct, *st;
    __half *qkvh, *yh, *xh, *wqh, *woh;
    cudaGetSymbolAddress((void**)&qkvh, g_qkvh);
    cudaGetSymbolAddress((void**)&yh,   g_yh);
    cudaGetSymbolAddress((void**)&xh,   g_xh);
    cudaGetSymbolAddress((void**)&wqh,  g_wqh);
    cudaGetSymbolAddress((void**)&woh,  g_woh);
    cudaGetSymbolAddress((void**)&ct,   g_cos);
    cudaGetSymbolAddress((void**)&st,   g_sin);

    // 1. tables + operand conversion
    rope_table_kernel<<<(SEQ * HALF + 255) / 256, 256>>>(ct, st);
    half_copy_kernel<<<(int)(((size_t)NTOK * DIMV / 4 + 255) / 256), 256>>>(
        x, xh, (size_t)NTOK * DIMV / 4);
    transpose_half_kernel<<<dim3(QKVW / 32, DIMV / 32), dim3(32, 8)>>>(Wqkv, wqh, DIMV, QKVW);
    transpose_half_kernel<<<dim3(DIMV / 32, DIMV / 32), dim3(32, 8)>>>(Wout, woh, DIMV, DIMV);

    // 2. QKV projection fused with RMS-norm + RoPE -> fp16 qkv
    cudaFuncSetAttribute(gemm1_fused_kernel, cudaFuncAttributeMaxDynamicSharedMemorySize, GSMEM_BYTES);
    gemm1_fused_kernel<<<dim3(QKVW / GBN, NTOK / GBM), 256, GSMEM_BYTES>>>(
        xh, wqh, qkvh, ct, st);

    // 3. causal GQA flash attention (fp16 mma, fp32 softmax/accum)
    cudaFuncSetAttribute(attn_f16_kernel, cudaFuncAttributeMaxDynamicSharedMemorySize, AT_SMEM_BYTES);
    attn_f16_kernel<<<dim3(SEQ / 128, BATCH * NHEAD), 256, AT_SMEM_BYTES>>>(qkvh, yh);

    // 4. output projection (fp16 mma, fp32 accum)
    cudaFuncSetAttribute(gemm_f16_kernel, cudaFuncAttributeMaxDynamicSharedMemorySize, GSMEM_BYTES);
    gemm_f16_kernel<<<dim3(DIMV / GBN, NTOK / GBM), 256, GSMEM_BYTES>>>(
        yh, woh, out, NTOK, DIMV, DIMV);
}

// round 8
// speedup vs baseline: 8.7796x; 1.1645x over previous
#include <cuda_runtime.h>
#include <cuda_fp16.h>
#include <math.h>
#include <math_constants.h>
#include <cstdint>

// ---------------- problem constants ----------------
#define DIMV   2048
#define SEQ    2048
#define BATCH  4
#define NHEAD  16
#define NKV    4
#define HD     128
#define HALF   64
#define QKVW   (DIMV + 2 * NKV * HD)   // 3072
#define NTOK   (BATCH * SEQ)           // 8192
#define RMS_EPS 1.1920929e-07f
#define ATT_SCALE 0.08838834764831845f // 1/sqrt(128)

// ---------------- scratch ----------------
__device__ __half g_qkvh[(size_t)NTOK * QKVW];   // 48 MB
__device__ __half g_yh[(size_t)NTOK * DIMV];     // 32 MB
__device__ __half g_xh[(size_t)NTOK * DIMV];     // 32 MB
__device__ __half g_wqh[(size_t)QKVW * DIMV];    // 12 MB (W_qkv^T, [N][K])
__device__ __half g_woh[(size_t)DIMV * DIMV];    //  8 MB (W_out^T, [N][K])
__device__ float  g_cos[SEQ * HALF];
__device__ float  g_sin[SEQ * HALF];

// ---------------- helpers ----------------
__device__ __forceinline__ void cp_async16(void* dst_smem, const void* src_gmem) {
    unsigned d = (unsigned)__cvta_generic_to_shared(dst_smem);
    asm volatile("cp.async.cg.shared.global [%0], [%1], 16;\n" :: "r"(d), "l"(src_gmem));
}
#define CP_COMMIT asm volatile("cp.async.commit_group;\n" ::: "memory")
#define CP_WAIT0  asm volatile("cp.async.wait_group 0;\n" ::: "memory")
#define CP_WAIT1  asm volatile("cp.async.wait_group 1;\n" ::: "memory")

__device__ __forceinline__ uint32_t smem_u32(const void* p) {
    uint32_t a;
    asm("{ .reg .u64 t; cvta.to.shared.u64 t, %1; cvt.u32.u64 %0, t; }" : "=r"(a) : "l"(p));
    return a;
}
__device__ __forceinline__ void ldsm_x4(uint32_t addr, unsigned* r) {
    asm volatile("ldmatrix.sync.aligned.m8n8.x4.shared.b16 {%0,%1,%2,%3}, [%4];"
                 : "=r"(r[0]), "=r"(r[1]), "=r"(r[2]), "=r"(r[3]) : "r"(addr));
}
__device__ __forceinline__ void ldsm_x4_t(uint32_t addr, unsigned* r) {
    asm volatile("ldmatrix.sync.aligned.m8n8.x4.trans.shared.b16 {%0,%1,%2,%3}, [%4];"
                 : "=r"(r[0]), "=r"(r[1]), "=r"(r[2]), "=r"(r[3]) : "r"(addr));
}
__device__ __forceinline__ void mma_f16(float* c, const unsigned* a, const unsigned* b) {
    asm volatile(
        "mma.sync.aligned.m16n8k16.row.col.f32.f16.f16.f32 "
        "{%0,%1,%2,%3}, {%4,%5,%6,%7}, {%8,%9}, {%0,%1,%2,%3};\n"
        : "+f"(c[0]), "+f"(c[1]), "+f"(c[2]), "+f"(c[3])
        : "r"(a[0]), "r"(a[1]), "r"(a[2]), "r"(a[3]), "r"(b[0]), "r"(b[1]));
}
__device__ __forceinline__ unsigned packh2(float lo, float hi) {
    __half2 h = __halves2half2(__float2half_rn(lo), __float2half_rn(hi));
    return *(unsigned*)&h;
}

// ======================================================================
// Merged prep: RoPE tables | x->half | Wqkv transpose+half | Wout transpose+half
// ======================================================================
#define PREP_ROPE   512
#define PREP_X      16384
#define PREP_WQ     (96 * 64)
#define PREP_WO     (64 * 64)
#define PREP_BLOCKS (PREP_ROPE + PREP_X + PREP_WQ + PREP_WO)

__global__ __launch_bounds__(256) void prep_kernel(
    const float* __restrict__ x, const float* __restrict__ Wqkv, const float* __restrict__ Wout,
    __half* __restrict__ xh, __half* __restrict__ wqh, __half* __restrict__ woh,
    float* __restrict__ ct, float* __restrict__ st)
{
    __shared__ float t[32][33];
    const int bx = blockIdx.x;
    const int tid = threadIdx.x;

    if (bx < PREP_ROPE) {
        int idx = bx * 256 + tid;
        int s = idx >> 6;
        int f = idx & 63;
        double inv = pow(10000.0, -((double)(2 * f)) / 128.0);
        double th = (double)s * inv;
        ct[idx] = (float)cos(th);
        st[idx] = (float)sin(th);
        return;
    }
    if (bx < PREP_ROPE + PREP_X) {
        size_t i = (size_t)(bx - PREP_ROPE) * 256 + tid;
        float4 v = ((const float4*)x)[i];
        ((__half2*)xh)[2 * i]     = __halves2half2(__float2half_rn(v.x), __float2half_rn(v.y));
        ((__half2*)xh)[2 * i + 1] = __halves2half2(__float2half_rn(v.z), __float2half_rn(v.w));
        return;
    }
    const float* src;
    __half* dst;
    int R, C, b;
    if (bx < PREP_ROPE + PREP_X + PREP_WQ) {
        b = bx - (PREP_ROPE + PREP_X);
        src = Wqkv; dst = wqh; R = DIMV; C = QKVW;
        int cb = b % 96, rb = b / 96;
        int c0 = cb * 32, r0 = rb * 32;
        int tx = tid & 31, ty = tid >> 5;
#pragma unroll
        for (int j = 0; j < 4; j++)
            t[ty + j * 8][tx] = src[(size_t)(r0 + ty + j * 8) * C + c0 + tx];
        __syncthreads();
#pragma unroll
        for (int j = 0; j < 4; j++)
            dst[(size_t)(c0 + ty + j * 8) * R + r0 + tx] = __float2half_rn(t[tx][ty + j * 8]);
        return;
    }
    b = bx - (PREP_ROPE + PREP_X + PREP_WQ);
    src = Wout; dst = woh; R = DIMV; C = DIMV;
    {
        int cb = b % 64, rb = b / 64;
        int c0 = cb * 32, r0 = rb * 32;
        int tx = tid & 31, ty = tid >> 5;
#pragma unroll
        for (int j = 0; j < 4; j++)
            t[ty + j * 8][tx] = src[(size_t)(r0 + ty + j * 8) * C + c0 + tx];
        __syncthreads();
#pragma unroll
        for (int j = 0; j < 4; j++)
            dst[(size_t)(c0 + ty + j * 8) * R + r0 + tx] = __float2half_rn(t[tx][ty + j * 8]);
    }
}

// ---------------- GEMM geometry: CTA 128x128, warp 64x32, BK=64, 3 stages ----------------
#define GBM 128
#define GBN 128
#define GBK 64
#define GA_BYTES (GBM * GBK * 2)           // 16384
#define GB_BYTES (GBN * GBK * 2)           // 16384
#define GSTAGE_BYTES (GA_BYTES + GB_BYTES) // 32768
#define GSMEM_BYTES (3 * GSTAGE_BYTES)     // 98304

#define GEMM_MAINLOOP(Aptr, Bptr, Kdim)                                            \
    auto issue_load = [&](int bufi, int k0) {                                      \
        char* s = smc + bufi * GSTAGE_BYTES;                                       \
        _Pragma("unroll")                                                          \
        for (int rep = 0; rep < 4; rep++) {                                        \
            int idx = tid + rep * 256;                                             \
            int m = idx >> 3, c16 = idx & 7;                                       \
            cp_async16(s + m * 128 + ((c16 ^ (m & 7)) << 4),                       \
                       (Aptr) + (size_t)(row0 + m) * (Kdim) + k0 + c16 * 8);       \
        }                                                                          \
        char* sb = s + GA_BYTES;                                                   \
        _Pragma("unroll")                                                          \
        for (int rep = 0; rep < 4; rep++) {                                        \
            int idx = tid + rep * 256;                                             \
            int n = idx >> 3, c16 = idx & 7;                                       \
            cp_async16(sb + n * 128 + ((c16 ^ (n & 7)) << 4),                      \
                       (Bptr) + (size_t)(col0 + n) * (Kdim) + k0 + c16 * 8);       \
        }                                                                          \
    };                                                                             \
    const int NIT = (Kdim) / GBK;                                                  \
    const int arow_off = ((lane >> 3) & 1) * 8 + (lane & 7);                       \
    const int aseg_hi  = lane >> 4;                                                \
    const int brow_off = ((lane >> 4) & 1) * 8 + (lane & 7);                       \
    const int bseg_hi  = (lane >> 3) & 1;                                          \
    issue_load(0, 0); CP_COMMIT;                                                   \
    issue_load(1, GBK); CP_COMMIT;                                                 \
    int buf = 0, nbuf = 2;                                                         \
    for (int it = 0; it < NIT; it++) {                                             \
        CP_WAIT1;                                                                  \
        __syncthreads();                                                           \
        if (it + 2 < NIT) issue_load(nbuf, (it + 2) * GBK);                        \
        CP_COMMIT;                                                                 \
        const uint32_t sA = sbase + buf * GSTAGE_BYTES;                            \
        const uint32_t sB = sA + GA_BYTES;                                         \
        _Pragma("unroll")                                                          \
        for (int ks = 0; ks < 4; ks++) {                                           \
            unsigned af[4][4], bfr[2][4];                                          \
            _Pragma("unroll")                                                      \
            for (int mt = 0; mt < 4; mt++) {                                       \
                int rrow = wm * 64 + mt * 16 + arow_off;                           \
                int seg = ks * 2 + aseg_hi;                                        \
                ldsm_x4(sA + rrow * 128 + ((seg ^ (rrow & 7)) << 4), af[mt]);      \
            }                                                                      \
            _Pragma("unroll")                                                      \
            for (int p = 0; p < 2; p++) {                                          \
                int rrow = wn * 32 + p * 16 + brow_off;                            \
                int seg = ks * 2 + bseg_hi;                                        \
                ldsm_x4(sB + rrow * 128 + ((seg ^ (rrow & 7)) << 4), bfr[p]);      \
            }                                                                      \
            _Pragma("unroll")                                                      \
            for (int mt = 0; mt < 4; mt++)                                         \
                _Pragma("unroll")                                                  \
                for (int nt = 0; nt < 4; nt++)                                     \
                    mma_f16(acc[mt][nt], af[mt],                                   \
                            (nt & 1) ? &bfr[nt >> 1][2] : &bfr[nt >> 1][0]);       \
        }                                                                          \
        __syncthreads();                                                           \
        buf = (buf == 2) ? 0 : buf + 1;                                            \
        nbuf = (nbuf == 2) ? 0 : nbuf + 1;                                         \
    }

// ======================================================================
// GEMM1 fused: qkvh = rmsnorm+rope( x @ Wqkv ) as fp16.
// CTA tile 128x128 = exactly ONE head. blockIdx.x: 0..15 Q, 16..19 K, 20..23 V.
// ======================================================================
#define XS_STRIDE 132
#define PR_OFF (128 * XS_STRIDE * 4)       // 67584; pr float[128][4] after xs

__global__ __launch_bounds__(256, 2) void gemm1_fused_kernel(
    const __half* __restrict__ A, const __half* __restrict__ Bt,
    __half* __restrict__ qkvh,
    const float* __restrict__ ct, const float* __restrict__ st)
{
    extern __shared__ char smc[];
    const uint32_t sbase = smem_u32(smc);
    const int tid = threadIdx.x;
    const int warp = tid >> 5;
    const int lane = tid & 31;
    const int grp = lane >> 2;
    const int tig = lane & 3;
    const int wm = warp >> 2;       // 2 row bands of 64
    const int wn = warp & 3;        // 4 col bands of 32
    const int row0 = blockIdx.y * GBM;
    const int col0 = blockIdx.x * GBN;

    float acc[4][4][4];
#pragma unroll
    for (int mt = 0; mt < 4; mt++)
#pragma unroll
        for (int nt = 0; nt < 4; nt++)
#pragma unroll
            for (int r = 0; r < 4; r++) acc[mt][nt][r] = 0.f;

    GEMM_MAINLOOP(A, Bt, DIMV)

    if (blockIdx.x >= 20) {
        // ---- V heads: plain half convert ----
#pragma unroll
        for (int mt = 0; mt < 4; mt++) {
            int row = row0 + wm * 64 + mt * 16 + grp;
#pragma unroll
            for (int nt = 0; nt < 4; nt++) {
                int col = col0 + wn * 32 + nt * 8 + tig * 2;
                *(unsigned*)(qkvh + (size_t)row * QKVW + col) =
                    packh2(acc[mt][nt][0], acc[mt][nt][1]);
                *(unsigned*)(qkvh + (size_t)(row + 8) * QKVW + col) =
                    packh2(acc[mt][nt][2], acc[mt][nt][3]);
            }
        }
        return;
    }

    // ---- Q/K heads: fused RMS-norm + RoPE over this 128-col head ----
    float* xs = (float*)smc;                 // [128][132]
    float* pr = (float*)(smc + PR_OFF);      // [128][4]

    // per-thread sum of squares (this warp's 32-col band), reduce over tig group
#pragma unroll
    for (int mt = 0; mt < 4; mt++) {
        float s0 = 0.f, s1 = 0.f;
#pragma unroll
        for (int nt = 0; nt < 4; nt++) {
            s0 += acc[mt][nt][0] * acc[mt][nt][0] + acc[mt][nt][1] * acc[mt][nt][1];
            s1 += acc[mt][nt][2] * acc[mt][nt][2] + acc[mt][nt][3] * acc[mt][nt][3];
        }
        s0 += __shfl_xor_sync(0xffffffffu, s0, 1);
        s0 += __shfl_xor_sync(0xffffffffu, s0, 2);
        s1 += __shfl_xor_sync(0xffffffffu, s1, 1);
        s1 += __shfl_xor_sync(0xffffffffu, s1, 2);
        if (tig == 0) {
            pr[(wm * 64 + mt * 16 + grp) * 4 + wn]     = s0;
            pr[(wm * 64 + mt * 16 + grp + 8) * 4 + wn] = s1;
        }
    }
    __syncthreads();

    // normalize into smem staging
#pragma unroll
    for (int mt = 0; mt < 4; mt++) {
        int r0l = wm * 64 + mt * 16 + grp;
        int r1l = r0l + 8;
        float sc0 = rsqrtf((pr[r0l * 4] + pr[r0l * 4 + 1] + pr[r0l * 4 + 2] + pr[r0l * 4 + 3])
                           * (1.0f / 128.0f) + RMS_EPS);
        float sc1 = rsqrtf((pr[r1l * 4] + pr[r1l * 4 + 1] + pr[r1l * 4 + 2] + pr[r1l * 4 + 3])
                           * (1.0f / 128.0f) + RMS_EPS);
#pragma unroll
        for (int nt = 0; nt < 4; nt++) {
            int col = wn * 32 + nt * 8 + tig * 2;
            xs[r0l * XS_STRIDE + col]     = acc[mt][nt][0] * sc0;
            xs[r0l * XS_STRIDE + col + 1] = acc[mt][nt][1] * sc0;
            xs[r1l * XS_STRIDE + col]     = acc[mt][nt][2] * sc1;
            xs[r1l * XS_STRIDE + col + 1] = acc[mt][nt][3] * sc1;
        }
    }
    __syncthreads();

    // RoPE: pair (f, f+64), f handled as float2 per lane; coalesced half2 stores
    const float2* ctp = (const float2*)ct;
    const float2* stp = (const float2*)st;
#pragma unroll 2
    for (int rr = 0; rr < 16; rr++) {
        int row = warp * 16 + rr;
        int s = (row0 + row) & (SEQ - 1);
        float2 xa = *(const float2*)&xs[row * XS_STRIDE + 2 * lane];
        float2 xb = *(const float2*)&xs[row * XS_STRIDE + 64 + 2 * lane];
        float2 c = ctp[s * 32 + lane];
        float2 sn = stp[s * 32 + lane];
        unsigned lo = packh2(xa.x * c.x + xb.x * sn.x, xa.y * c.y + xb.y * sn.y);
        unsigned hi = packh2(xb.x * c.x - xa.x * sn.x, xb.y * c.y - xa.y * sn.y);
        size_t gb = (size_t)(row0 + row) * QKVW + col0 + 2 * lane;
        *(unsigned*)(qkvh + gb)      = lo;
        *(unsigned*)(qkvh + gb + 64) = hi;
    }
}

// ======================================================================
// GEMM2: out[M,N] fp32 = A[M,K] @ Bt[N,K]^T
// ======================================================================
__global__ __launch_bounds__(256, 2) void gemm_f16_kernel(
    const __half* __restrict__ A, const __half* __restrict__ Bt, float* __restrict__ C,
    int M, int N, int K)
{
    extern __shared__ char smc[];
    const uint32_t sbase = smem_u32(smc);
    const int tid = threadIdx.x;
    const int warp = tid >> 5;
    const int lane = tid & 31;
    const int grp = lane >> 2;
    const int tig = lane & 3;
    const int wm = warp >> 2;
    const int wn = warp & 3;
    const int row0 = blockIdx.y * GBM;
    const int col0 = blockIdx.x * GBN;

    float acc[4][4][4];
#pragma unroll
    for (int mt = 0; mt < 4; mt++)
#pragma unroll
        for (int nt = 0; nt < 4; nt++)
#pragma unroll
            for (int r = 0; r < 4; r++) acc[mt][nt][r] = 0.f;

    GEMM_MAINLOOP(A, Bt, K)

#pragma unroll
    for (int mt = 0; mt < 4; mt++) {
        int row = row0 + wm * 64 + mt * 16 + grp;
#pragma unroll
        for (int nt = 0; nt < 4; nt++) {
            int col = col0 + wn * 32 + nt * 8 + tig * 2;
            *(float2*)(C + (size_t)row * N + col) =
                make_float2(acc[mt][nt][0], acc[mt][nt][1]);
            *(float2*)(C + (size_t)(row + 8) * N + col) =
                make_float2(acc[mt][nt][2], acc[mt][nt][3]);
        }
    }
}

// ======================================================================
// FP16 flash attention (R7 + warp-level skip of fully masked key tiles)
// ======================================================================
#define AT_SMEM_BYTES 65536

__global__ __launch_bounds__(256, 1) void attn_f16_kernel(
    const __half* __restrict__ qkvh, __half* __restrict__ yh)
{
    extern __shared__ char smc[];
    const uint32_t sbase = smem_u32(smc);
    const int tid = threadIdx.x;
    const int warp = tid >> 5;
    const int lane = tid & 31;
    const int grp = lane >> 2;
    const int tig = lane & 3;

    const int i0 = (gridDim.x - 1 - blockIdx.x) * 128;
    const int bh = blockIdx.y;
    const int b = bh >> 4;
    const int h = bh & 15;
    const int kvh = h >> 2;

    const size_t rowb = (size_t)b * SEQ * QKVW;
    const int qcol = h * HD;
    const int kcol = DIMV + kvh * HD;
    const int vcol = DIMV + NKV * HD + kvh * HD;

#pragma unroll
    for (int rep = 0; rep < 8; rep++) {
        int idx = tid + rep * 256;
        int row = idx >> 4, seg = idx & 15;
        cp_async16(smc + row * 256 + ((seg ^ (row & 7)) << 4),
                   qkvh + rowb + (size_t)(i0 + row) * QKVW + qcol + seg * 8);
    }
    CP_COMMIT; CP_WAIT0;
    __syncthreads();

    const int arow_off = ((lane >> 3) & 1) * 8 + (lane & 7);
    const int aseg_hi  = lane >> 4;
    unsigned qf[8][4];
    {
        int row = warp * 16 + arow_off;
#pragma unroll
        for (int ks = 0; ks < 8; ks++) {
            int seg = ks * 2 + aseg_hi;
            ldsm_x4(sbase + row * 256 + ((seg ^ (row & 7)) << 4), qf[ks]);
        }
    }
    __syncthreads();

    auto issue_kv = [&](int buf, int j0) {
        char* Ks = smc + buf * 32768;
        char* Vs = Ks + 16384;
#pragma unroll
        for (int rep = 0; rep < 4; rep++) {
            int idx = tid + rep * 256;
            int row = idx >> 4, seg = idx & 15;
            const __half* kr = qkvh + rowb + (size_t)(j0 + row) * QKVW;
            uint32_t d = row * 256 + ((seg ^ (row & 7)) << 4);
            cp_async16(Ks + d, kr + kcol + seg * 8);
            cp_async16(Vs + d, kr + vcol + seg * 8);
        }
    };

    float of[16][4];
#pragma unroll
    for (int nf = 0; nf < 16; nf++)
#pragma unroll
        for (int r = 0; r < 4; r++) of[nf][r] = 0.f;
    float m0 = -CUDART_INF_F, m1 = -CUDART_INF_F, l0 = 0.f, l1 = 0.f;

    const int qi0 = i0 + warp * 16 + grp;
    const int qi1 = qi0 + 8;
    const int wrow_max = i0 + warp * 16 + 15;   // warp-uniform last Q row
    const int NIT = (i0 + 128) / 64;

    const int brow_off = ((lane >> 4) & 1) * 8 + (lane & 7);
    const int bseg_hi  = (lane >> 3) & 1;
    const int vrow_off = ((lane >> 3) & 1) * 8 + (lane & 7);
    const int vseg_hi  = (lane >> 4) & 1;

    issue_kv(0, 0); CP_COMMIT;

    for (int it = 0; it < NIT; it++) {
        const int j0 = it * 64;
        const int buf = it & 1;
        if (it + 1 < NIT) issue_kv(buf ^ 1, j0 + 64);
        CP_COMMIT;
        CP_WAIT1;
        __syncthreads();

        if (j0 <= wrow_max) {   // warp-uniform: skip fully masked key tiles
            const uint32_t Kb = sbase + buf * 32768;
            const uint32_t Vb = Kb + 16384;

            float sacc[8][4];
#pragma unroll
            for (int nf = 0; nf < 8; nf++)
#pragma unroll
                for (int r = 0; r < 4; r++) sacc[nf][r] = 0.f;

#pragma unroll
            for (int ks = 0; ks < 8; ks++) {
                unsigned bf[4][4];
#pragma unroll
                for (int p = 0; p < 4; p++) {
                    int row = p * 16 + brow_off;
                    int seg = ks * 2 + bseg_hi;
                    ldsm_x4(Kb + row * 256 + ((seg ^ (row & 7)) << 4), bf[p]);
                }
#pragma unroll
                for (int nf = 0; nf < 8; nf++)
                    mma_f16(sacc[nf], qf[ks], (nf & 1) ? &bf[nf >> 1][2] : &bf[nf >> 1][0]);
            }

            if (j0 + 63 > i0) {
#pragma unroll
                for (int nf = 0; nf < 8; nf++) {
                    int key = j0 + nf * 8 + 2 * tig;
                    if (key     > qi0) sacc[nf][0] = -CUDART_INF_F;
                    if (key + 1 > qi0) sacc[nf][1] = -CUDART_INF_F;
                    if (key     > qi1) sacc[nf][2] = -CUDART_INF_F;
                    if (key + 1 > qi1) sacc[nf][3] = -CUDART_INF_F;
                }
            }

            float mx0 = -CUDART_INF_F, mx1 = -CUDART_INF_F;
#pragma unroll
            for (int nf = 0; nf < 8; nf++) {
                mx0 = fmaxf(mx0, fmaxf(sacc[nf][0], sacc[nf][1]));
                mx1 = fmaxf(mx1, fmaxf(sacc[nf][2], sacc[nf][3]));
            }
            mx0 = fmaxf(mx0, __shfl_xor_sync(0xffffffffu, mx0, 1));
            mx0 = fmaxf(mx0, __shfl_xor_sync(0xffffffffu, mx0, 2));
            mx1 = fmaxf(mx1, __shfl_xor_sync(0xffffffffu, mx1, 1));
            mx1 = fmaxf(mx1, __shfl_xor_sync(0xffffffffu, mx1, 2));

            float m0n = fmaxf(m0, mx0);
            float m1n = fmaxf(m1, mx1);
            float alpha0 = __expf((m0 - m0n) * ATT_SCALE);
            float alpha1 = __expf((m1 - m1n) * ATT_SCALE);
            m0 = m0n; m1 = m1n;

            unsigned ph[8][2];
            float rs0 = 0.f, rs1 = 0.f;
#pragma unroll
            for (int nf = 0; nf < 8; nf++) {
                float p0 = __expf((sacc[nf][0] - m0) * ATT_SCALE);
                float p1 = __expf((sacc[nf][1] - m0) * ATT_SCALE);
                float p2 = __expf((sacc[nf][2] - m1) * ATT_SCALE);
                float p3 = __expf((sacc[nf][3] - m1) * ATT_SCALE);
                rs0 += p0 + p1;
                rs1 += p2 + p3;
                ph[nf][0] = packh2(p0, p1);
                ph[nf][1] = packh2(p2, p3);
            }
            rs0 += __shfl_xor_sync(0xffffffffu, rs0, 1);
            rs0 += __shfl_xor_sync(0xffffffffu, rs0, 2);
            rs1 += __shfl_xor_sync(0xffffffffu, rs1, 1);
            rs1 += __shfl_xor_sync(0xffffffffu, rs1, 2);
            l0 = l0 * alpha0 + rs0;
            l1 = l1 * alpha1 + rs1;

#pragma unroll
            for (int nf = 0; nf < 16; nf++) {
                of[nf][0] *= alpha0; of[nf][1] *= alpha0;
                of[nf][2] *= alpha1; of[nf][3] *= alpha1;
            }

#pragma unroll
            for (int ks = 0; ks < 4; ks++) {
                unsigned af[4] = {ph[2 * ks][0], ph[2 * ks][1],
                                  ph[2 * ks + 1][0], ph[2 * ks + 1][1]};
#pragma unroll
                for (int p = 0; p < 8; p++) {
                    int row = ks * 16 + vrow_off;
                    int seg = p * 2 + vseg_hi;
                    unsigned vf[4];
                    ldsm_x4_t(Vb + row * 256 + ((seg ^ (row & 7)) << 4), vf);
                    mma_f16(of[2 * p],     af, &vf[0]);
                    mma_f16(of[2 * p + 1], af, &vf[2]);
                }
            }
        }
        __syncthreads();
    }

    float inv0 = 1.0f / l0, inv1 = 1.0f / l1;
    int r0 = i0 + warp * 16 + grp;
    __half* dst0 = yh + (size_t)(b * SEQ + r0) * DIMV + h * HD;
    __half* dst1 = yh + (size_t)(b * SEQ + r0 + 8) * DIMV + h * HD;
#pragma unroll
    for (int nf = 0; nf < 16; nf++) {
        *(unsigned*)(dst0 + nf * 8 + 2 * tig) = packh2(of[nf][0] * inv0, of[nf][1] * inv0);
        *(unsigned*)(dst1 + nf * 8 + 2 * tig) = packh2(of[nf][2] * inv1, of[nf][3] * inv1);
    }
}

// ================= launch =================
extern "C" void kernel_launch(void* const* d_in, const int* in_sizes, int n_in,
                              void* d_out, int out_size)
{
    const float* x    = (const float*)d_in[0];
    const float* Wqkv = (const float*)d_in[1];
    const float* Wout = (const float*)d_in[2];
    float* out = (float*)d_out;

    float *ct, *st;
    __half *qkvh, *yh, *xh, *wqh, *woh;
    cudaGetSymbolAddress((void**)&qkvh, g_qkvh);
    cudaGetSymbolAddress((void**)&yh,   g_yh);
    cudaGetSymbolAddress((void**)&xh,   g_xh);
    cudaGetSymbolAddress((void**)&wqh,  g_wqh);
    cudaGetSymbolAddress((void**)&woh,  g_woh);
    cudaGetSymbolAddress((void**)&ct,   g_cos);
    cudaGetSymbolAddress((void**)&st,   g_sin);

    // 1. merged prep (tables + conversions + transposes)
    prep_kernel<<<PREP_BLOCKS, 256>>>(x, Wqkv, Wout, xh, wqh, woh, ct, st);

    // 2. QKV projection fused with RMS-norm + RoPE -> fp16 qkv
    cudaFuncSetAttribute(gemm1_fused_kernel, cudaFuncAttributeMaxDynamicSharedMemorySize, GSMEM_BYTES);
    gemm1_fused_kernel<<<dim3(QKVW / GBN, NTOK / GBM), 256, GSMEM_BYTES>>>(
        xh, wqh, qkvh, ct, st);

    // 3. causal GQA flash attention
    cudaFuncSetAttribute(attn_f16_kernel, cudaFuncAttributeMaxDynamicSharedMemorySize, AT_SMEM_BYTES);
    attn_f16_kernel<<<dim3(SEQ / 128, BATCH * NHEAD), 256, AT_SMEM_BYTES>>>(qkvh, yh);

    // 4. output projection
    cudaFuncSetAttribute(gemm_f16_kernel, cudaFuncAttributeMaxDynamicSharedMemorySize, GSMEM_BYTES);
    gemm_f16_kernel<<<dim3(DIMV / GBN, NTOK / GBM), 256, GSMEM_BYTES>>>(
        yh, woh, out, NTOK, DIMV, DIMV);
}